// round 12
// baseline (speedup 1.0000x reference)
#include <cuda_runtime.h>
#include <cstdint>

#define BSZ 1024

// ---------------- static device buffers ----------------
__device__ int8_t g_c0[BSZ*30*30*64];
__device__ int8_t g_c1[BSZ*28*28*64];
__device__ int8_t g_p1[BSZ*14*14*64];
__device__ int8_t g_c2[BSZ*12*12*128];
__device__ int8_t g_c3[BSZ*10*10*128];
__device__ int8_t g_p3[BSZ*5*5*128];
__device__ int8_t g_c4[BSZ*3*3*256];
__device__ int8_t g_c5[BSZ*256];
__device__ int8_t g_f0[BSZ*512];
__device__ int8_t g_f1[BSZ*512];

__device__ int8_t g_w0[64*36];
__device__ int8_t g_w1[64*592];
__device__ int8_t g_w2[128*592];
__device__ int8_t g_w3[128*1168];
__device__ int8_t g_w4[256*1168];
__device__ int8_t g_w5[256*2304];     // [oc][9][256] im2col order (gemm)
__device__ int8_t g_wf0[512*256];
__device__ int8_t g_wf1[512*512];
__device__ int8_t g_wf2[10*512];

__device__ float g_bns[6*256], g_bnm[6*256], g_bnb[6*256];
__device__ float g_fns[2*512], g_fnm[2*512], g_fnb[2*512];

// ---------------- helpers ----------------
__device__ __forceinline__ int8_t qtern(float y){
    float r = rintf(y);
    r = fminf(fmaxf(r, -1.f), 1.f);
    return (int8_t)r;
}

__device__ __forceinline__ void mma_s8(int* c, int a0,int a1,int a2,int a3,int b0,int b1){
    asm volatile(
        "mma.sync.aligned.m16n8k32.row.col.s32.s8.s8.s32 "
        "{%0,%1,%2,%3},{%4,%5,%6,%7},{%8,%9},{%0,%1,%2,%3};"
        : "+r"(c[0]),"+r"(c[1]),"+r"(c[2]),"+r"(c[3])
        : "r"(a0),"r"(a1),"r"(a2),"r"(a3),"r"(b0),"r"(b1));
}

__device__ __forceinline__ void ldsm_x4(uint32_t addr, int& r0,int& r1,int& r2,int& r3){
    asm volatile("ldmatrix.sync.aligned.m8n8.x4.shared.b16 {%0,%1,%2,%3}, [%4];"
        : "=r"(r0),"=r"(r1),"=r"(r2),"=r"(r3) : "r"(addr));
}

__device__ __forceinline__ int8_t wq(float v){
    float r = rintf(v);
    r = fminf(fmaxf(r, -1.f), 1.f);
    return (int8_t)r;
}

__device__ __forceinline__ uint32_t smem_u32(const void* p){
    uint32_t a;
    asm("{ .reg .u64 t; cvta.to.shared.u64 t, %1; cvt.u32.u64 %0, t; }" : "=r"(a) : "l"(p));
    return a;
}

// ---------------- single merged prep kernel (weights + bn) ----------------
__device__ __forceinline__ void wq_conv(const float* __restrict__ src, int8_t* dst,
                                        int CI, int CIP, int KP, int idx){
    int c  = idx % CIP;
    int k  = (idx / CIP) % 9;
    int oc = idx / (9*CIP);
    int8_t q = 0;
    if (c < CI) q = wq(src[(size_t)(oc*CI + c)*9 + k]);
    dst[(size_t)oc*KP + k*CIP + c] = q;
}

__global__ void k_prep_all(const float* wc0,const float* wc1,const float* wc2,
                           const float* wc3,const float* wc4,const float* wc5,
                           const float* wf0,const float* wf1,const float* wf2,
                           const float* b0,const float* b1,const float* b2,
                           const float* b3,const float* b4,const float* b5,
                           const float* f0,const float* f1){
    int idx = blockIdx.x*256 + threadIdx.x;
    if (idx < 2304)  { wq_conv(wc0, g_w0, 3,  4,  36,  idx); return; }  idx -= 2304;
    if (idx < 36864) { wq_conv(wc1, g_w1, 64, 64, 592, idx); return; }  idx -= 36864;
    if (idx < 73728) { wq_conv(wc2, g_w2, 64, 64, 592, idx); return; }  idx -= 73728;
    if (idx < 147456){ wq_conv(wc3, g_w3, 128,128,1168,idx); return; }  idx -= 147456;
    if (idx < 294912){ wq_conv(wc4, g_w4, 128,128,1168,idx); return; }  idx -= 294912;
    if (idx < 589824){ wq_conv(wc5, g_w5, 256,256,2304,idx); return; }  idx -= 589824;
    if (idx < 131072){ g_wf0[idx] = wq(wf0[idx]); return; }             idx -= 131072;
    if (idx < 262144){ g_wf1[idx] = wq(wf1[idx]); return; }             idx -= 262144;
    if (idx < 5120)  { g_wf2[idx] = wq(wf2[idx]); return; }             idx -= 5120;
    if (idx < 1536){
        const float* srcs[6] = {b0,b1,b2,b3,b4,b5};
        const int    chs [6] = {64,64,128,128,256,256};
        int seg = idx >> 8, c = idx & 255;
        int C = chs[seg];
        if (c < C){
            const float* p = srcs[seg];
            g_bns[seg*256+c] = p[c] / sqrtf(p[3*C+c] + 1e-4f);
            g_bnm[seg*256+c] = p[2*C+c];
            g_bnb[seg*256+c] = p[C+c];
        }
        return;
    }
    idx -= 1536;
    if (idx < 1024){
        int k = idx >> 9, c = idx & 511;
        const float* p = k ? f1 : f0;
        g_fns[k*512+c] = p[c] / sqrtf(p[1536+c] + 1e-4f);
        g_fnm[k*512+c] = p[1024+c];
        g_fnb[k*512+c] = p[512+c];
    }
}

// ---------------- conv0: fused inquant + dp4a conv ----------------
__global__ void __launch_bounds__(256) k_conv0(
    const float* __restrict__ x, const int8_t* __restrict__ wt,
    const float* __restrict__ bs, const float* __restrict__ bm, const float* __restrict__ bb,
    int8_t* __restrict__ out)
{
    __shared__ int8_t s_w[64*36];
    __shared__ int    s_in[1024];
    const int tid = threadIdx.x;
    const int img = blockIdx.x;

    {
        const int4* src = (const int4*)wt;
        int4* dst = (int4*)s_w;
        for (int i = tid; i < 144; i += 256) dst[i] = src[i];
    }
    {
        const float* xb = x + (size_t)img*3072;
        for (int i = tid; i < 1024; i += 256){
            char4 r; float v;
            v = rintf(xb[i]     *128.f); v = fminf(fmaxf(v,-128.f),127.f); r.x = (signed char)v;
            v = rintf(xb[1024+i]*128.f); v = fminf(fmaxf(v,-128.f),127.f); r.y = (signed char)v;
            v = rintf(xb[2048+i]*128.f); v = fminf(fmaxf(v,-128.f),127.f); r.z = (signed char)v;
            r.w = 0;
            s_in[i] = *(int*)&r;
        }
    }
    __syncthreads();

    constexpr int TOT = 900*4;
    for (int t = tid; t < TOT; t += 256){
        int pix = t % 900;
        int ocg = t / 900;
        int oy = pix / 30, ox = pix % 30;
        int acc[16];
        #pragma unroll
        for (int j=0;j<16;j++) acc[j]=0;
        const int8_t* wb_ = s_w + ocg*16*36;

        #pragma unroll
        for (int ky=0; ky<3; ky++){
            #pragma unroll
            for (int kx=0; kx<3; kx++){
                const int a  = s_in[(oy+ky)*32 + ox + kx];
                const int kk = ky*3 + kx;
                #pragma unroll
                for (int j=0;j<16;j++){
                    int w = *(const int*)(wb_ + (j*9 + kk)*4);
                    acc[j] = __dp4a(a, w, acc[j]);
                }
            }
        }
        union { int8_t b[16]; int4 v; } q;
        #pragma unroll
        for (int j=0;j<16;j++){
            int oc = ocg*16 + j;
            float y = ((float)acc[j]*(1.0f/128.0f) - bm[oc]) * bs[oc] + bb[oc];
            q.b[j] = qtern(y);
        }
        *(int4*)(out + ((size_t)img*900 + pix)*64 + ocg*16) = q.v;
    }
}

// ---------------- implicit-GEMM conv via ldmatrix + mma.sync ----------------
// 8 m-warps x 1 n-warp: each warp owns 16*AT rows and ALL 64 oc (NT=8).
template<int CIN,int COUT,int OCT,int HIN,int WIN,int NIMG,int AT>
__global__ void __launch_bounds__(256) k_cmma(
    const int8_t* __restrict__ in, const int8_t* __restrict__ wt,
    const float* __restrict__ bs, const float* __restrict__ bm, const float* __restrict__ bb,
    int8_t* __restrict__ out)
{
    constexpr int HOUT = HIN-2, WOUT = WIN-2;
    constexpr int NPIX = HOUT*WOUT, INPIX = HIN*WIN;
    constexpr int K  = 9*CIN, KP = K+16, SA = CIN+16;
    constexpr int CH = K/32;
    constexpr int CPT = CIN/32;
    constexpr int NT = OCT/8;
    constexpr int NP = NT/2;
    constexpr int AW = NIMG*INPIX*SA;
    constexpr int MROW = 16*AT;
    constexpr int CTAROW = 8*MROW;
    constexpr int MT = (NIMG*NPIX + CTAROW-1)/CTAROW;

    extern __shared__ int8_t smem[];
    int8_t* s_a = smem;
    int8_t* s_w = smem + AW;

    const int tid  = threadIdx.x;
    const int img0 = blockIdx.x * NIMG;
    const int NI   = (BSZ - img0 < NIMG) ? (BSZ - img0) : NIMG;
    const int NROWSE = NI*NPIX;
    const int ocb  = blockIdx.y * OCT;
    const int lane = tid & 31;
    const int wm   = tid >> 5;

    {
        constexpr int RV = CIN/16;
        const int4* src = (const int4*)(in + (size_t)img0*INPIX*CIN);
        const int tot = NI*INPIX*RV;
        #pragma unroll 4
        for (int i = tid; i < tot; i += 256){
            int row = i / RV, j = i % RV;
            ((int4*)s_a)[row*(SA/16) + j] = src[i];
        }
    }
    {
        const int4* src = (const int4*)(wt + (size_t)ocb*KP);
        int4* dst = (int4*)s_w;
        #pragma unroll 4
        for (int i = tid; i < OCT*KP/16; i += 256) dst[i] = src[i];
    }
    __syncthreads();

    const uint32_t s_a32 = smem_u32(s_a);
    const uint32_t s_w32 = smem_u32(s_w);

    uint32_t baddr[NP];
    #pragma unroll
    for (int p=0; p<NP; p++)
        baddr[p] = s_w32 + (uint32_t)((p*16 + ((lane>>4)<<3) + (lane&7))*KP
                                      + ((lane>>3)&1)*16);

    const int laneR = lane & 15;
    const int laneC = (lane >> 4) * 16;

    for (int mt = 0; mt < MT; mt++){
        const int rbase = mt*CTAROW + wm*MROW;

        uint32_t aA[AT];
        #pragma unroll
        for (int t=0; t<AT; t++){
            int r = rbase + 16*t + laneR;
            if (r >= NROWSE) r = 0;
            int im  = r / NPIX;
            int pix = r - im*NPIX;
            int py  = pix / WOUT;
            int px  = pix - py*WOUT;
            aA[t] = s_a32 + (uint32_t)((im*INPIX + py*WIN + px)*SA + laneC);
        }

        int acc[AT][NT][4];
        #pragma unroll
        for (int t=0;t<AT;t++)
            #pragma unroll
            for (int nt=0;nt<NT;nt++){ acc[t][nt][0]=acc[t][nt][1]=acc[t][nt][2]=acc[t][nt][3]=0; }

        #pragma unroll
        for (int ch = 0; ch < CH; ch++){
            const int kk = ch / CPT;
            const int cb = (ch % CPT)*32;
            const int aoff = ((kk/3)*WIN + (kk%3))*SA + cb;
            int a[AT][4];
            #pragma unroll
            for (int t=0;t<AT;t++)
                ldsm_x4(aA[t]+aoff, a[t][0],a[t][1],a[t][2],a[t][3]);
            int b[NT][2];
            #pragma unroll
            for (int p=0; p<NP; p++)
                ldsm_x4(baddr[p] + ch*32, b[2*p][0], b[2*p][1], b[2*p+1][0], b[2*p+1][1]);
            #pragma unroll
            for (int t=0;t<AT;t++)
                #pragma unroll
                for (int nt=0; nt<NT; nt++)
                    mma_s8(acc[t][nt], a[t][0],a[t][1],a[t][2],a[t][3], b[nt][0], b[nt][1]);
        }

        #pragma unroll
        for (int t=0; t<AT; t++){
            const int pa = rbase + 16*t + (lane>>2);
            const int pb = pa + 8;
            int ia = pa / NPIX, xa = pa - ia*NPIX;
            int ib = pb / NPIX, xb = pb - ib*NPIX;
            int8_t* oa = out + ((size_t)(img0+ia)*NPIX + xa)*COUT + ocb + (lane&3)*2;
            int8_t* ob = out + ((size_t)(img0+ib)*NPIX + xb)*COUT + ocb + (lane&3)*2;
            #pragma unroll
            for (int nt=0; nt<NT; nt++){
                const int col = ocb + nt*8 + (lane&3)*2;
                const float s0 = bs[col],   m0 = bm[col],   c0 = bb[col];
                const float s1 = bs[col+1], m1 = bm[col+1], c1 = bb[col+1];
                if (pa < NROWSE){
                    char2 o;
                    o.x = qtern(((float)acc[t][nt][0] - m0)*s0 + c0);
                    o.y = qtern(((float)acc[t][nt][1] - m1)*s1 + c1);
                    *(char2*)(oa + nt*8) = o;
                }
                if (pb < NROWSE){
                    char2 o;
                    o.x = qtern(((float)acc[t][nt][2] - m0)*s0 + c0);
                    o.y = qtern(((float)acc[t][nt][3] - m1)*s1 + c1);
                    *(char2*)(ob + nt*8) = o;
                }
            }
        }
    }
}

// ---------------- GEMM via ldmatrix + mma.sync (conv5/fc0/fc1) ----------------
template<int K,int N>
__global__ void __launch_bounds__(256) k_gemm(
    const int8_t* __restrict__ in, const int8_t* __restrict__ wt,
    const float* __restrict__ bs, const float* __restrict__ bm, const float* __restrict__ bb,
    int8_t* __restrict__ out)
{
    constexpr int KC = 256, SK = KC+16;
    extern __shared__ int8_t smem[];
    int8_t* s_a = smem;
    int8_t* s_b = smem + 64*SK;

    const int tid  = threadIdx.x;
    const int lane = tid & 31;
    const int warp = tid >> 5;
    const int wm   = warp & 1;
    const int wn   = warp >> 1;
    const int m0   = blockIdx.x * 64;
    const int n0   = blockIdx.y * 128;

    const uint32_t a32 = smem_u32(s_a);
    const uint32_t b32 = smem_u32(s_b);
    const int laneR = lane & 15;
    const int laneC = (lane >> 4) * 16;

    int acc[2][4][4];
    #pragma unroll
    for (int t=0;t<2;t++)
        #pragma unroll
        for (int nt=0;nt<4;nt++){ acc[t][nt][0]=acc[t][nt][1]=acc[t][nt][2]=acc[t][nt][3]=0; }

    for (int kc = 0; kc < K; kc += KC){
        if (kc) __syncthreads();
        for (int i = tid; i < 64*16; i += 256){
            int row = i >> 4, j = i & 15;
            ((int4*)s_a)[row*17 + j] = *(const int4*)(in + (size_t)(m0+row)*K + kc + j*16);
        }
        for (int i = tid; i < 128*16; i += 256){
            int row = i >> 4, j = i & 15;
            ((int4*)s_b)[row*17 + j] = *(const int4*)(wt + (size_t)(n0+row)*K + kc + j*16);
        }
        __syncthreads();

        #pragma unroll
        for (int ch = 0; ch < KC/32; ch++){
            int a0,a1,a2,a3,a4,a5,a6,a7;
            ldsm_x4(a32 + (wm*32 + laneR)*SK + laneC + ch*32,      a0,a1,a2,a3);
            ldsm_x4(a32 + (wm*32 + 16 + laneR)*SK + laneC + ch*32, a4,a5,a6,a7);
            int b[4][2];
            #pragma unroll
            for (int p=0; p<2; p++)
                ldsm_x4(b32 + (wn*32 + p*16 + ((lane>>4)<<3) + (lane&7))*SK
                            + ((lane>>3)&1)*16 + ch*32,
                        b[2*p][0], b[2*p][1], b[2*p+1][0], b[2*p+1][1]);
            #pragma unroll
            for (int nt=0; nt<4; nt++){
                mma_s8(acc[0][nt], a0,a1,a2,a3, b[nt][0], b[nt][1]);
                mma_s8(acc[1][nt], a4,a5,a6,a7, b[nt][0], b[nt][1]);
            }
        }
    }

    #pragma unroll
    for (int nt=0; nt<4; nt++){
        const int col = n0 + wn*32 + nt*8 + (lane&3)*2;
        const float s0 = bs[col],   m_ = bm[col],   b0_ = bb[col];
        const float s1 = bs[col+1], m1 = bm[col+1], b1_ = bb[col+1];
        #pragma unroll
        for (int t=0; t<2; t++){
            const int ra = m0 + wm*32 + 16*t + (lane>>2);
            char2 o;
            o.x = qtern(((float)acc[t][nt][0] - m_)*s0 + b0_);
            o.y = qtern(((float)acc[t][nt][1] - m1)*s1 + b1_);
            *(char2*)(out + (size_t)ra*N + col) = o;
            o.x = qtern(((float)acc[t][nt][2] - m_)*s0 + b0_);
            o.y = qtern(((float)acc[t][nt][3] - m1)*s1 + b1_);
            *(char2*)(out + (size_t)(ra+8)*N + col) = o;
        }
    }
}

// ---------------- pool ----------------
template<int C,int HIN,int WIN>
__global__ void k_pool(const int8_t* __restrict__ in, int8_t* __restrict__ out){
    constexpr int HO=HIN/2, WO=WIN/2, C4=C/4;
    constexpr int TOT = BSZ*HO*WO*C4;
    int idx = blockIdx.x*256 + threadIdx.x;
    if (idx >= TOT) return;
    int c4 = idx % C4;
    int rr = idx / C4;
    int ox = rr % WO; rr /= WO;
    int oy = rr % HO;
    int b  = rr / HO;
    const int8_t* base = in + ((size_t)(b*HIN + 2*oy)*WIN + 2*ox)*C + c4*4;
    char4 a0 = *(const char4*)base;
    char4 a1 = *(const char4*)(base + C);
    char4 a2 = *(const char4*)(base + (size_t)WIN*C);
    char4 a3 = *(const char4*)(base + (size_t)WIN*C + C);
    char4 o;
    o.x = qtern((float)(a0.x+a1.x+a2.x+a3.x) * 0.25f);
    o.y = qtern((float)(a0.y+a1.y+a2.y+a3.y) * 0.25f);
    o.z = qtern((float)(a0.z+a1.z+a2.z+a3.z) * 0.25f);
    o.w = qtern((float)(a0.w+a1.w+a2.w+a3.w) * 0.25f);
    ((char4*)out)[idx] = o;
}

// ---------------- last FC + TensorNorm ----------------
__global__ void k_fc_last(const int8_t* __restrict__ in, const int8_t* __restrict__ wt,
                          const float* __restrict__ tn, float* __restrict__ out){
    __shared__ int8_t s_a[512];
    int b = blockIdx.x, tid = threadIdx.x;
    for (int i = tid; i < 32; i += 256)
        ((int4*)s_a)[i] = ((const int4*)(in + (size_t)b*512))[i];
    __syncthreads();
    if (tid < 10){
        const int4* wr = (const int4*)(wt + (size_t)tid*512);
        int acc = 0;
        #pragma unroll 8
        for (int c=0;c<32;c++){
            int4 a = ((const int4*)s_a)[c];
            int4 w = wr[c];
            acc=__dp4a(a.x,w.x,acc); acc=__dp4a(a.y,w.y,acc);
            acc=__dp4a(a.z,w.z,acc); acc=__dp4a(a.w,w.w,acc);
        }
        float y = ((float)acc - tn[2]) / sqrtf(tn[3] + 1e-4f) * tn[0] + tn[1];
        out[b*10 + tid] = y;
    }
}

// ---------------- host ----------------
extern "C" void kernel_launch(void* const* d_in, const int* in_sizes, int n_in,
                              void* d_out, int out_size)
{
    const float *x=0, *wc[6]={0,0,0,0,0,0}, *bnc[6]={0,0,0,0,0,0};
    const float *wf[3]={0,0,0}, *bnf[2]={0,0}, *tn=0;
    int n256=0, n512=0, n1024=0, n2048=0;
    for (int i=0;i<n_in;i++){
        const float* p = (const float*)d_in[i];
        switch (in_sizes[i]){
            case 3145728: x = p; break;
            case 1728:    wc[0]=p; break;
            case 36864:   wc[1]=p; break;
            case 73728:   wc[2]=p; break;
            case 147456:  wc[3]=p; break;
            case 294912:  wc[4]=p; break;
            case 589824:  wc[5]=p; break;
            case 131072:  wf[0]=p; break;
            case 262144:  wf[1]=p; break;
            case 5120:    wf[2]=p; break;
            case 256:     if(n256 <2) bnc[0+n256++ ]=p; break;
            case 512:     if(n512 <2) bnc[2+n512++ ]=p; break;
            case 1024:    if(n1024<2) bnc[4+n1024++]=p; break;
            case 2048:    if(n2048<2) bnf[n2048++  ]=p; break;
            case 4:       tn = p; break;
            default: break;
        }
    }

    int8_t *c0,*c1,*p1,*c2,*c3,*p3,*c4,*c5,*f0,*f1;
    int8_t *w0,*w1,*w2,*w3,*w4,*w5,*wf0d,*wf1d,*wf2d;
    float *bns,*bnm,*bnb,*fns,*fnm,*fnb;
    cudaGetSymbolAddress((void**)&c0, g_c0);
    cudaGetSymbolAddress((void**)&c1, g_c1);  cudaGetSymbolAddress((void**)&p1, g_p1);
    cudaGetSymbolAddress((void**)&c2, g_c2);  cudaGetSymbolAddress((void**)&c3, g_c3);
    cudaGetSymbolAddress((void**)&p3, g_p3);  cudaGetSymbolAddress((void**)&c4, g_c4);
    cudaGetSymbolAddress((void**)&c5, g_c5);  cudaGetSymbolAddress((void**)&f0, g_f0);
    cudaGetSymbolAddress((void**)&f1, g_f1);
    cudaGetSymbolAddress((void**)&w0, g_w0);  cudaGetSymbolAddress((void**)&w1, g_w1);
    cudaGetSymbolAddress((void**)&w2, g_w2);  cudaGetSymbolAddress((void**)&w3, g_w3);
    cudaGetSymbolAddress((void**)&w4, g_w4);  cudaGetSymbolAddress((void**)&w5, g_w5);
    cudaGetSymbolAddress((void**)&wf0d, g_wf0); cudaGetSymbolAddress((void**)&wf1d, g_wf1);
    cudaGetSymbolAddress((void**)&wf2d, g_wf2);
    cudaGetSymbolAddress((void**)&bns, g_bns); cudaGetSymbolAddress((void**)&bnm, g_bnm);
    cudaGetSymbolAddress((void**)&bnb, g_bnb);
    cudaGetSymbolAddress((void**)&fns, g_fns); cudaGetSymbolAddress((void**)&fnm, g_fnm);
    cudaGetSymbolAddress((void**)&fnb, g_fnb);

    const int T = 256;
    const int GSM = 64*272 + 128*272;            // 52,224 gemm smem

    // launch 0: all weights + all bn (merged)
    k_prep_all<<<(1545984+T-1)/T, T>>>(wc[0],wc[1],wc[2],wc[3],wc[4],wc[5],
                                       wf[0],wf[1],wf[2],
                                       bnc[0],bnc[1],bnc[2],bnc[3],bnc[4],bnc[5],
                                       bnf[0],bnf[1]);
    // launch 1: conv0 (fused inquant)
    k_conv0<<<1024, T>>>(x, w0, bns, bnm, bnb, c0);
    // launch 2: conv1 — 8m x 1n, AT=2, NIMG=1 (110KB smem, 2 CTA/SM)
    {
        const int SM = 1*900*80 + 64*592;        // 109,888
        cudaFuncSetAttribute(k_cmma<64,64,64,30,30,1,2>,
                             cudaFuncAttributeMaxDynamicSharedMemorySize, SM);
        k_cmma<64,64,64,30,30,1,2><<<dim3(1024,1), T, SM>>>(c0, w1, bns+256, bnm+256, bnb+256, c1);
    }
    // launch 3: pool1
    k_pool<64,28,28><<<(BSZ*14*14*16+T-1)/T, T>>>(c1, p1);
    // launch 4: conv2 — NIMG=4 (100.6KB smem, 2 CTA/SM)
    {
        const int SM = 4*196*80 + 64*592;        // 100,608
        cudaFuncSetAttribute(k_cmma<64,128,64,14,14,4,2>,
                             cudaFuncAttributeMaxDynamicSharedMemorySize, SM);
        k_cmma<64,128,64,14,14,4,2><<<dim3(256,2), T, SM>>>(p1, w2, bns+512, bnm+512, bnb+512, c2);
    }
    // launch 5: conv3 — NIMG=5 (178.4KB, 1 CTA/SM; NPIX=100 leaves no 2-CTA option)
    {
        const int SM = 5*144*144 + 64*1168;      // 178,432
        cudaFuncSetAttribute(k_cmma<128,128,64,12,12,5,2>,
                             cudaFuncAttributeMaxDynamicSharedMemorySize, SM);
        k_cmma<128,128,64,12,12,5,2><<<dim3(205,2), T, SM>>>(c2, w3, bns+768, bnm+768, bnb+768, c3);
    }
    // launch 6: pool3
    k_pool<128,10,10><<<(BSZ*5*5*32+T-1)/T, T>>>(c3, p3);
    // launch 7: conv4 — NIMG=10 (110.8KB smem, 2 CTA/SM)
    {
        const int SM = 10*25*144 + 64*1168;      // 110,752
        cudaFuncSetAttribute(k_cmma<128,256,64,5,5,10,2>,
                             cudaFuncAttributeMaxDynamicSharedMemorySize, SM);
        k_cmma<128,256,64,5,5,10,2><<<dim3(103,4), T, SM>>>(p3, w4, bns+1024, bnm+1024, bnb+1024, c4);
    }
    // launch 8: conv5 as GEMM (M=1024, N=256, K=2304)
    cudaFuncSetAttribute(k_gemm<2304,256>, cudaFuncAttributeMaxDynamicSharedMemorySize, GSM);
    k_gemm<2304,256><<<dim3(16,2), T, GSM>>>(c4, w5, bns+1280, bnm+1280, bnb+1280, c5);
    // launch 9: fc0 (K=256, N=512)
    cudaFuncSetAttribute(k_gemm<256,512>, cudaFuncAttributeMaxDynamicSharedMemorySize, GSM);
    k_gemm<256,512><<<dim3(16,4), T, GSM>>>(c5, wf0d, fns, fnm, fnb, f0);
    // launch 10: fc1 (K=512, N=512)
    cudaFuncSetAttribute(k_gemm<512,512>, cudaFuncAttributeMaxDynamicSharedMemorySize, GSM);
    k_gemm<512,512><<<dim3(16,4), T, GSM>>>(f0, wf1d, fns+512, fnm+512, fnb+512, f1);
    // launch 11: fc2 + TensorNorm
    k_fc_last<<<BSZ, T>>>(f1, wf2d, tn, (float*)d_out);
}

// round 14
// speedup vs baseline: 1.0633x; 1.0633x over previous
#include <cuda_runtime.h>
#include <cstdint>

#define BSZ 1024

// ---------------- static device buffers ----------------
__device__ int8_t g_c0[BSZ*30*30*64];
__device__ int8_t g_c1[BSZ*28*28*64];
__device__ int8_t g_p1[BSZ*14*14*64];
__device__ int8_t g_c2[BSZ*12*12*128];
__device__ int8_t g_c3[BSZ*10*10*128];
__device__ int8_t g_p3[BSZ*5*5*128];
__device__ int8_t g_c4[BSZ*3*3*256];
__device__ int8_t g_c5[BSZ*256];
__device__ int8_t g_f0[BSZ*512];
__device__ int8_t g_f1[BSZ*512];

__device__ int8_t g_w0[64*36];
__device__ int8_t g_w1[64*592];
__device__ int8_t g_w2[128*592];
__device__ int8_t g_w3[128*1168];
__device__ int8_t g_w4[256*1168];
__device__ int8_t g_w5[256*2304];     // [oc][9][256] im2col order (gemm)
__device__ int8_t g_wf0[512*256];
__device__ int8_t g_wf1[512*512];
__device__ int8_t g_wf2[10*512];

__device__ float g_bns[6*256], g_bnm[6*256], g_bnb[6*256];
__device__ float g_fns[2*512], g_fnm[2*512], g_fnb[2*512];

// ---------------- helpers ----------------
__device__ __forceinline__ int8_t qtern(float y){
    float r = rintf(y);
    r = fminf(fmaxf(r, -1.f), 1.f);
    return (int8_t)r;
}

__device__ __forceinline__ void mma_s8(int* c, int a0,int a1,int a2,int a3,int b0,int b1){
    asm volatile(
        "mma.sync.aligned.m16n8k32.row.col.s32.s8.s8.s32 "
        "{%0,%1,%2,%3},{%4,%5,%6,%7},{%8,%9},{%0,%1,%2,%3};"
        : "+r"(c[0]),"+r"(c[1]),"+r"(c[2]),"+r"(c[3])
        : "r"(a0),"r"(a1),"r"(a2),"r"(a3),"r"(b0),"r"(b1));
}

__device__ __forceinline__ void ldsm_x4(uint32_t addr, int& r0,int& r1,int& r2,int& r3){
    asm volatile("ldmatrix.sync.aligned.m8n8.x4.shared.b16 {%0,%1,%2,%3}, [%4];"
        : "=r"(r0),"=r"(r1),"=r"(r2),"=r"(r3) : "r"(addr));
}

__device__ __forceinline__ int8_t wq(float v){
    float r = rintf(v);
    r = fminf(fmaxf(r, -1.f), 1.f);
    return (int8_t)r;
}

__device__ __forceinline__ uint32_t smem_u32(const void* p){
    uint32_t a;
    asm("{ .reg .u64 t; cvta.to.shared.u64 t, %1; cvt.u32.u64 %0, t; }" : "=r"(a) : "l"(p));
    return a;
}

// ---------------- single merged prep kernel (weights + bn) ----------------
__device__ __forceinline__ void wq_conv(const float* __restrict__ src, int8_t* dst,
                                        int CI, int CIP, int KP, int idx){
    int c  = idx % CIP;
    int k  = (idx / CIP) % 9;
    int oc = idx / (9*CIP);
    int8_t q = 0;
    if (c < CI) q = wq(src[(size_t)(oc*CI + c)*9 + k]);
    dst[(size_t)oc*KP + k*CIP + c] = q;
}

__global__ void k_prep_all(const float* wc0,const float* wc1,const float* wc2,
                           const float* wc3,const float* wc4,const float* wc5,
                           const float* wf0,const float* wf1,const float* wf2,
                           const float* b0,const float* b1,const float* b2,
                           const float* b3,const float* b4,const float* b5,
                           const float* f0,const float* f1){
    int idx = blockIdx.x*256 + threadIdx.x;
    if (idx < 2304)  { wq_conv(wc0, g_w0, 3,  4,  36,  idx); return; }  idx -= 2304;
    if (idx < 36864) { wq_conv(wc1, g_w1, 64, 64, 592, idx); return; }  idx -= 36864;
    if (idx < 73728) { wq_conv(wc2, g_w2, 64, 64, 592, idx); return; }  idx -= 73728;
    if (idx < 147456){ wq_conv(wc3, g_w3, 128,128,1168,idx); return; }  idx -= 147456;
    if (idx < 294912){ wq_conv(wc4, g_w4, 128,128,1168,idx); return; }  idx -= 294912;
    if (idx < 589824){ wq_conv(wc5, g_w5, 256,256,2304,idx); return; }  idx -= 589824;
    if (idx < 131072){ g_wf0[idx] = wq(wf0[idx]); return; }             idx -= 131072;
    if (idx < 262144){ g_wf1[idx] = wq(wf1[idx]); return; }             idx -= 262144;
    if (idx < 5120)  { g_wf2[idx] = wq(wf2[idx]); return; }             idx -= 5120;
    if (idx < 1536){
        const float* srcs[6] = {b0,b1,b2,b3,b4,b5};
        const int    chs [6] = {64,64,128,128,256,256};
        int seg = idx >> 8, c = idx & 255;
        int C = chs[seg];
        if (c < C){
            const float* p = srcs[seg];
            g_bns[seg*256+c] = p[c] / sqrtf(p[3*C+c] + 1e-4f);
            g_bnm[seg*256+c] = p[2*C+c];
            g_bnb[seg*256+c] = p[C+c];
        }
        return;
    }
    idx -= 1536;
    if (idx < 1024){
        int k = idx >> 9, c = idx & 511;
        const float* p = k ? f1 : f0;
        g_fns[k*512+c] = p[c] / sqrtf(p[1536+c] + 1e-4f);
        g_fnm[k*512+c] = p[1024+c];
        g_fnb[k*512+c] = p[512+c];
    }
}

// ---------------- conv0: fused inquant + dp4a conv ----------------
__global__ void __launch_bounds__(256) k_conv0(
    const float* __restrict__ x, const int8_t* __restrict__ wt,
    const float* __restrict__ bs, const float* __restrict__ bm, const float* __restrict__ bb,
    int8_t* __restrict__ out)
{
    __shared__ int8_t s_w[64*36];
    __shared__ int    s_in[1024];
    const int tid = threadIdx.x;
    const int img = blockIdx.x;

    {
        const int4* src = (const int4*)wt;
        int4* dst = (int4*)s_w;
        for (int i = tid; i < 144; i += 256) dst[i] = src[i];
    }
    {
        const float* xb = x + (size_t)img*3072;
        for (int i = tid; i < 1024; i += 256){
            char4 r; float v;
            v = rintf(xb[i]     *128.f); v = fminf(fmaxf(v,-128.f),127.f); r.x = (signed char)v;
            v = rintf(xb[1024+i]*128.f); v = fminf(fmaxf(v,-128.f),127.f); r.y = (signed char)v;
            v = rintf(xb[2048+i]*128.f); v = fminf(fmaxf(v,-128.f),127.f); r.z = (signed char)v;
            r.w = 0;
            s_in[i] = *(int*)&r;
        }
    }
    __syncthreads();

    constexpr int TOT = 900*4;
    for (int t = tid; t < TOT; t += 256){
        int pix = t % 900;
        int ocg = t / 900;
        int oy = pix / 30, ox = pix % 30;
        int acc[16];
        #pragma unroll
        for (int j=0;j<16;j++) acc[j]=0;
        const int8_t* wb_ = s_w + ocg*16*36;

        #pragma unroll
        for (int ky=0; ky<3; ky++){
            #pragma unroll
            for (int kx=0; kx<3; kx++){
                const int a  = s_in[(oy+ky)*32 + ox + kx];
                const int kk = ky*3 + kx;
                #pragma unroll
                for (int j=0;j<16;j++){
                    int w = *(const int*)(wb_ + (j*9 + kk)*4);
                    acc[j] = __dp4a(a, w, acc[j]);
                }
            }
        }
        union { int8_t b[16]; int4 v; } q;
        #pragma unroll
        for (int j=0;j<16;j++){
            int oc = ocg*16 + j;
            float y = ((float)acc[j]*(1.0f/128.0f) - bm[oc]) * bs[oc] + bb[oc];
            q.b[j] = qtern(y);
        }
        *(int4*)(out + ((size_t)img*900 + pix)*64 + ocg*16) = q.v;
    }
}

// ---------------- implicit-GEMM conv via ldmatrix + mma.sync ----------------
// 8 m-warps x 1 n-warp: each warp owns 16*AT rows and ALL 64 oc (NT=8).
template<int CIN,int COUT,int OCT,int HIN,int WIN,int NIMG,int AT>
__global__ void __launch_bounds__(256) k_cmma(
    const int8_t* __restrict__ in, const int8_t* __restrict__ wt,
    const float* __restrict__ bs, const float* __restrict__ bm, const float* __restrict__ bb,
    int8_t* __restrict__ out)
{
    constexpr int HOUT = HIN-2, WOUT = WIN-2;
    constexpr int NPIX = HOUT*WOUT, INPIX = HIN*WIN;
    constexpr int K  = 9*CIN, KP = K+16, SA = CIN+16;
    constexpr int CH = K/32;
    constexpr int CPT = CIN/32;
    constexpr int NT = OCT/8;
    constexpr int NP = NT/2;
    constexpr int AW = NIMG*INPIX*SA;
    constexpr int MROW = 16*AT;
    constexpr int CTAROW = 8*MROW;
    constexpr int MT = (NIMG*NPIX + CTAROW-1)/CTAROW;

    extern __shared__ int8_t smem[];
    int8_t* s_a = smem;
    int8_t* s_w = smem + AW;

    const int tid  = threadIdx.x;
    const int img0 = blockIdx.x * NIMG;
    const int NI   = (BSZ - img0 < NIMG) ? (BSZ - img0) : NIMG;
    const int NROWSE = NI*NPIX;
    const int ocb  = blockIdx.y * OCT;
    const int lane = tid & 31;
    const int wm   = tid >> 5;

    {
        constexpr int RV = CIN/16;
        const int4* src = (const int4*)(in + (size_t)img0*INPIX*CIN);
        const int tot = NI*INPIX*RV;
        #pragma unroll 4
        for (int i = tid; i < tot; i += 256){
            int row = i / RV, j = i % RV;
            ((int4*)s_a)[row*(SA/16) + j] = src[i];
        }
    }
    {
        const int4* src = (const int4*)(wt + (size_t)ocb*KP);
        int4* dst = (int4*)s_w;
        #pragma unroll 4
        for (int i = tid; i < OCT*KP/16; i += 256) dst[i] = src[i];
    }
    __syncthreads();

    const uint32_t s_a32 = smem_u32(s_a);
    const uint32_t s_w32 = smem_u32(s_w);

    uint32_t baddr[NP];
    #pragma unroll
    for (int p=0; p<NP; p++)
        baddr[p] = s_w32 + (uint32_t)((p*16 + ((lane>>4)<<3) + (lane&7))*KP
                                      + ((lane>>3)&1)*16);

    const int laneR = lane & 15;
    const int laneC = (lane >> 4) * 16;

    for (int mt = 0; mt < MT; mt++){
        const int rbase = mt*CTAROW + wm*MROW;

        uint32_t aA[AT];
        #pragma unroll
        for (int t=0; t<AT; t++){
            int r = rbase + 16*t + laneR;
            if (r >= NROWSE) r = 0;
            int im  = r / NPIX;
            int pix = r - im*NPIX;
            int py  = pix / WOUT;
            int px  = pix - py*WOUT;
            aA[t] = s_a32 + (uint32_t)((im*INPIX + py*WIN + px)*SA + laneC);
        }

        int acc[AT][NT][4];
        #pragma unroll
        for (int t=0;t<AT;t++)
            #pragma unroll
            for (int nt=0;nt<NT;nt++){ acc[t][nt][0]=acc[t][nt][1]=acc[t][nt][2]=acc[t][nt][3]=0; }

        #pragma unroll
        for (int ch = 0; ch < CH; ch++){
            const int kk = ch / CPT;
            const int cb = (ch % CPT)*32;
            const int aoff = ((kk/3)*WIN + (kk%3))*SA + cb;
            int a[AT][4];
            #pragma unroll
            for (int t=0;t<AT;t++)
                ldsm_x4(aA[t]+aoff, a[t][0],a[t][1],a[t][2],a[t][3]);
            int b[NT][2];
            #pragma unroll
            for (int p=0; p<NP; p++)
                ldsm_x4(baddr[p] + ch*32, b[2*p][0], b[2*p][1], b[2*p+1][0], b[2*p+1][1]);
            #pragma unroll
            for (int t=0;t<AT;t++)
                #pragma unroll
                for (int nt=0; nt<NT; nt++)
                    mma_s8(acc[t][nt], a[t][0],a[t][1],a[t][2],a[t][3], b[nt][0], b[nt][1]);
        }

        #pragma unroll
        for (int t=0; t<AT; t++){
            const int pa = rbase + 16*t + (lane>>2);
            const int pb = pa + 8;
            int ia = pa / NPIX, xa = pa - ia*NPIX;
            int ib = pb / NPIX, xb = pb - ib*NPIX;
            int8_t* oa = out + ((size_t)(img0+ia)*NPIX + xa)*COUT + ocb + (lane&3)*2;
            int8_t* ob = out + ((size_t)(img0+ib)*NPIX + xb)*COUT + ocb + (lane&3)*2;
            #pragma unroll
            for (int nt=0; nt<NT; nt++){
                const int col = ocb + nt*8 + (lane&3)*2;
                const float s0 = bs[col],   m0 = bm[col],   c0 = bb[col];
                const float s1 = bs[col+1], m1 = bm[col+1], c1 = bb[col+1];
                if (pa < NROWSE){
                    char2 o;
                    o.x = qtern(((float)acc[t][nt][0] - m0)*s0 + c0);
                    o.y = qtern(((float)acc[t][nt][1] - m1)*s1 + c1);
                    *(char2*)(oa + nt*8) = o;
                }
                if (pb < NROWSE){
                    char2 o;
                    o.x = qtern(((float)acc[t][nt][2] - m0)*s0 + c0);
                    o.y = qtern(((float)acc[t][nt][3] - m1)*s1 + c1);
                    *(char2*)(ob + nt*8) = o;
                }
            }
        }
    }
}

// ---------------- GEMM via ldmatrix + mma.sync (conv5/fc0/fc1) ----------------
template<int K,int N>
__global__ void __launch_bounds__(256) k_gemm(
    const int8_t* __restrict__ in, const int8_t* __restrict__ wt,
    const float* __restrict__ bs, const float* __restrict__ bm, const float* __restrict__ bb,
    int8_t* __restrict__ out)
{
    constexpr int KC = 256, SK = KC+16;
    extern __shared__ int8_t smem[];
    int8_t* s_a = smem;
    int8_t* s_b = smem + 64*SK;

    const int tid  = threadIdx.x;
    const int lane = tid & 31;
    const int warp = tid >> 5;
    const int wm   = warp & 1;
    const int wn   = warp >> 1;
    const int m0   = blockIdx.x * 64;
    const int n0   = blockIdx.y * 128;

    const uint32_t a32 = smem_u32(s_a);
    const uint32_t b32 = smem_u32(s_b);
    const int laneR = lane & 15;
    const int laneC = (lane >> 4) * 16;

    int acc[2][4][4];
    #pragma unroll
    for (int t=0;t<2;t++)
        #pragma unroll
        for (int nt=0;nt<4;nt++){ acc[t][nt][0]=acc[t][nt][1]=acc[t][nt][2]=acc[t][nt][3]=0; }

    for (int kc = 0; kc < K; kc += KC){
        if (kc) __syncthreads();
        for (int i = tid; i < 64*16; i += 256){
            int row = i >> 4, j = i & 15;
            ((int4*)s_a)[row*17 + j] = *(const int4*)(in + (size_t)(m0+row)*K + kc + j*16);
        }
        for (int i = tid; i < 128*16; i += 256){
            int row = i >> 4, j = i & 15;
            ((int4*)s_b)[row*17 + j] = *(const int4*)(wt + (size_t)(n0+row)*K + kc + j*16);
        }
        __syncthreads();

        #pragma unroll
        for (int ch = 0; ch < KC/32; ch++){
            int a0,a1,a2,a3,a4,a5,a6,a7;
            ldsm_x4(a32 + (wm*32 + laneR)*SK + laneC + ch*32,      a0,a1,a2,a3);
            ldsm_x4(a32 + (wm*32 + 16 + laneR)*SK + laneC + ch*32, a4,a5,a6,a7);
            int b[4][2];
            #pragma unroll
            for (int p=0; p<2; p++)
                ldsm_x4(b32 + (wn*32 + p*16 + ((lane>>4)<<3) + (lane&7))*SK
                            + ((lane>>3)&1)*16 + ch*32,
                        b[2*p][0], b[2*p][1], b[2*p+1][0], b[2*p+1][1]);
            #pragma unroll
            for (int nt=0; nt<4; nt++){
                mma_s8(acc[0][nt], a0,a1,a2,a3, b[nt][0], b[nt][1]);
                mma_s8(acc[1][nt], a4,a5,a6,a7, b[nt][0], b[nt][1]);
            }
        }
    }

    #pragma unroll
    for (int nt=0; nt<4; nt++){
        const int col = n0 + wn*32 + nt*8 + (lane&3)*2;
        const float s0 = bs[col],   m_ = bm[col],   b0_ = bb[col];
        const float s1 = bs[col+1], m1 = bm[col+1], b1_ = bb[col+1];
        #pragma unroll
        for (int t=0; t<2; t++){
            const int ra = m0 + wm*32 + 16*t + (lane>>2);
            char2 o;
            o.x = qtern(((float)acc[t][nt][0] - m_)*s0 + b0_);
            o.y = qtern(((float)acc[t][nt][1] - m1)*s1 + b1_);
            *(char2*)(out + (size_t)ra*N + col) = o;
            o.x = qtern(((float)acc[t][nt][2] - m_)*s0 + b0_);
            o.y = qtern(((float)acc[t][nt][3] - m1)*s1 + b1_);
            *(char2*)(out + (size_t)(ra+8)*N + col) = o;
        }
    }
}

// ---------------- pool: SIMD byte avg+quant (ternary-exact) ----------------
// sum of 4 ternary bytes in [-4,4]; avg+rint(half-even)+clip == (+1 iff s>=3, -1 iff s<=-3)
template<int C,int HIN,int WIN>
__global__ void k_pool(const int8_t* __restrict__ in, int8_t* __restrict__ out){
    constexpr int HO=HIN/2, WO=WIN/2, C16=C/16;
    constexpr int TOT = BSZ*HO*WO*C16;
    int idx = blockIdx.x*256 + threadIdx.x;
    if (idx >= TOT) return;
    int c16 = idx % C16;
    int rr = idx / C16;
    int ox = rr % WO; rr /= WO;
    int oy = rr % HO;
    int b  = rr / HO;
    const int8_t* base = in + ((size_t)(b*HIN + 2*oy)*WIN + 2*ox)*C + c16*16;
    int4 a0 = *(const int4*)base;
    int4 a1 = *(const int4*)(base + C);
    int4 a2 = *(const int4*)(base + (size_t)WIN*C);
    int4 a3 = *(const int4*)(base + (size_t)WIN*C + C);
    int4 o;
    #define PQ(x0,x1,x2,x3) ({ \
        unsigned s_ = __vadd4(__vadd4((unsigned)(x0),(unsigned)(x1)), \
                              __vadd4((unsigned)(x2),(unsigned)(x3))); \
        (int)((__vcmpges4(s_, 0x03030303u) & 0x01010101u) | __vcmples4(s_, 0xFDFDFDFDu)); })
    o.x = PQ(a0.x,a1.x,a2.x,a3.x);
    o.y = PQ(a0.y,a1.y,a2.y,a3.y);
    o.z = PQ(a0.z,a1.z,a2.z,a3.z);
    o.w = PQ(a0.w,a1.w,a2.w,a3.w);
    #undef PQ
    ((int4*)out)[idx] = o;
}

// ---------------- last FC + TensorNorm ----------------
__global__ void k_fc_last(const int8_t* __restrict__ in, const int8_t* __restrict__ wt,
                          const float* __restrict__ tn, float* __restrict__ out){
    __shared__ int8_t s_a[512];
    int b = blockIdx.x, tid = threadIdx.x;
    for (int i = tid; i < 32; i += 256)
        ((int4*)s_a)[i] = ((const int4*)(in + (size_t)b*512))[i];
    __syncthreads();
    if (tid < 10){
        const int4* wr = (const int4*)(wt + (size_t)tid*512);
        int acc = 0;
        #pragma unroll 8
        for (int c=0;c<32;c++){
            int4 a = ((const int4*)s_a)[c];
            int4 w = wr[c];
            acc=__dp4a(a.x,w.x,acc); acc=__dp4a(a.y,w.y,acc);
            acc=__dp4a(a.z,w.z,acc); acc=__dp4a(a.w,w.w,acc);
        }
        float y = ((float)acc - tn[2]) / sqrtf(tn[3] + 1e-4f) * tn[0] + tn[1];
        out[b*10 + tid] = y;
    }
}

// ---------------- host ----------------
extern "C" void kernel_launch(void* const* d_in, const int* in_sizes, int n_in,
                              void* d_out, int out_size)
{
    const float *x=0, *wc[6]={0,0,0,0,0,0}, *bnc[6]={0,0,0,0,0,0};
    const float *wf[3]={0,0,0}, *bnf[2]={0,0}, *tn=0;
    int n256=0, n512=0, n1024=0, n2048=0;
    for (int i=0;i<n_in;i++){
        const float* p = (const float*)d_in[i];
        switch (in_sizes[i]){
            case 3145728: x = p; break;
            case 1728:    wc[0]=p; break;
            case 36864:   wc[1]=p; break;
            case 73728:   wc[2]=p; break;
            case 147456:  wc[3]=p; break;
            case 294912:  wc[4]=p; break;
            case 589824:  wc[5]=p; break;
            case 131072:  wf[0]=p; break;
            case 262144:  wf[1]=p; break;
            case 5120:    wf[2]=p; break;
            case 256:     if(n256 <2) bnc[0+n256++ ]=p; break;
            case 512:     if(n512 <2) bnc[2+n512++ ]=p; break;
            case 1024:    if(n1024<2) bnc[4+n1024++]=p; break;
            case 2048:    if(n2048<2) bnf[n2048++  ]=p; break;
            case 4:       tn = p; break;
            default: break;
        }
    }

    int8_t *c0,*c1,*p1,*c2,*c3,*p3,*c4,*c5,*f0,*f1;
    int8_t *w0,*w1,*w2,*w3,*w4,*w5,*wf0d,*wf1d,*wf2d;
    float *bns,*bnm,*bnb,*fns,*fnm,*fnb;
    cudaGetSymbolAddress((void**)&c0, g_c0);
    cudaGetSymbolAddress((void**)&c1, g_c1);  cudaGetSymbolAddress((void**)&p1, g_p1);
    cudaGetSymbolAddress((void**)&c2, g_c2);  cudaGetSymbolAddress((void**)&c3, g_c3);
    cudaGetSymbolAddress((void**)&p3, g_p3);  cudaGetSymbolAddress((void**)&c4, g_c4);
    cudaGetSymbolAddress((void**)&c5, g_c5);  cudaGetSymbolAddress((void**)&f0, g_f0);
    cudaGetSymbolAddress((void**)&f1, g_f1);
    cudaGetSymbolAddress((void**)&w0, g_w0);  cudaGetSymbolAddress((void**)&w1, g_w1);
    cudaGetSymbolAddress((void**)&w2, g_w2);  cudaGetSymbolAddress((void**)&w3, g_w3);
    cudaGetSymbolAddress((void**)&w4, g_w4);  cudaGetSymbolAddress((void**)&w5, g_w5);
    cudaGetSymbolAddress((void**)&wf0d, g_wf0); cudaGetSymbolAddress((void**)&wf1d, g_wf1);
    cudaGetSymbolAddress((void**)&wf2d, g_wf2);
    cudaGetSymbolAddress((void**)&bns, g_bns); cudaGetSymbolAddress((void**)&bnm, g_bnm);
    cudaGetSymbolAddress((void**)&bnb, g_bnb);
    cudaGetSymbolAddress((void**)&fns, g_fns); cudaGetSymbolAddress((void**)&fnm, g_fnm);
    cudaGetSymbolAddress((void**)&fnb, g_fnb);

    const int T = 256;
    const int GSM = 64*272 + 128*272;            // 52,224 gemm smem

    // launch 0: all weights + all bn (merged)
    k_prep_all<<<(1545984+T-1)/T, T>>>(wc[0],wc[1],wc[2],wc[3],wc[4],wc[5],
                                       wf[0],wf[1],wf[2],
                                       bnc[0],bnc[1],bnc[2],bnc[3],bnc[4],bnc[5],
                                       bnf[0],bnf[1]);
    // launch 1: conv0 (fused inquant)
    k_conv0<<<1024, T>>>(x, w0, bns, bnm, bnb, c0);
    // launch 2: conv1 — 8m x 1n, AT=2, NIMG=1 (110KB smem, 2 CTA/SM) [R10 best]
    {
        const int SM = 1*900*80 + 64*592;        // 109,888
        cudaFuncSetAttribute(k_cmma<64,64,64,30,30,1,2>,
                             cudaFuncAttributeMaxDynamicSharedMemorySize, SM);
        k_cmma<64,64,64,30,30,1,2><<<dim3(1024,1), T, SM>>>(c0, w1, bns+256, bnm+256, bnb+256, c1);
    }
    // launch 3: pool1 (SIMD)
    k_pool<64,28,28><<<(BSZ*14*14*4+T-1)/T, T>>>(c1, p1);
    // launch 4: conv2 — NIMG=8 [R10 best]
    {
        const int SM = 8*196*80 + 64*592;        // 163,328
        cudaFuncSetAttribute(k_cmma<64,128,64,14,14,8,2>,
                             cudaFuncAttributeMaxDynamicSharedMemorySize, SM);
        k_cmma<64,128,64,14,14,8,2><<<dim3(128,2), T, SM>>>(p1, w2, bns+512, bnm+512, bnb+512, c2);
    }
    // launch 5: conv3 — NIMG=5 [R10 best]
    {
        const int SM = 5*144*144 + 64*1168;      // 178,432
        cudaFuncSetAttribute(k_cmma<128,128,64,12,12,5,2>,
                             cudaFuncAttributeMaxDynamicSharedMemorySize, SM);
        k_cmma<128,128,64,12,12,5,2><<<dim3(205,2), T, SM>>>(c2, w3, bns+768, bnm+768, bnb+768, c3);
    }
    // launch 6: pool3 (SIMD)
    k_pool<128,10,10><<<(BSZ*5*5*8+T-1)/T, T>>>(c3, p3);
    // launch 7: conv4 — NIMG=28 [R10 best]
    {
        const int SM = 28*25*144 + 64*1168;      // 175,552
        cudaFuncSetAttribute(k_cmma<128,256,64,5,5,28,2>,
                             cudaFuncAttributeMaxDynamicSharedMemorySize, SM);
        k_cmma<128,256,64,5,5,28,2><<<dim3(37,4), T, SM>>>(p3, w4, bns+1024, bnm+1024, bnb+1024, c4);
    }
    // launch 8: conv5 as GEMM (M=1024, N=256, K=2304)
    cudaFuncSetAttribute(k_gemm<2304,256>, cudaFuncAttributeMaxDynamicSharedMemorySize, GSM);
    k_gemm<2304,256><<<dim3(16,2), T, GSM>>>(c4, w5, bns+1280, bnm+1280, bnb+1280, c5);
    // launch 9: fc0 (K=256, N=512)
    cudaFuncSetAttribute(k_gemm<256,512>, cudaFuncAttributeMaxDynamicSharedMemorySize, GSM);
    k_gemm<256,512><<<dim3(16,4), T, GSM>>>(c5, wf0d, fns, fnm, fnb, f0);
    // launch 10: fc1 (K=512, N=512)
    cudaFuncSetAttribute(k_gemm<512,512>, cudaFuncAttributeMaxDynamicSharedMemorySize, GSM);
    k_gemm<512,512><<<dim3(16,4), T, GSM>>>(f0, wf1d, fns+512, fnm+512, fnb+512, f1);
    // launch 11: fc2 + TensorNorm
    k_fc_last<<<BSZ, T>>>(f1, wf2d, tn, (float*)d_out);
}

// round 15
// speedup vs baseline: 1.0685x; 1.0049x over previous
#include <cuda_runtime.h>
#include <cstdint>

#define BSZ 1024

// ---------------- static device buffers ----------------
__device__ int8_t g_c0[BSZ*30*30*64];
__device__ int8_t g_c1[BSZ*28*28*64];
__device__ int8_t g_c2[BSZ*12*12*128];
__device__ int8_t g_c3[BSZ*10*10*128];
__device__ int8_t g_c4[BSZ*3*3*256];
__device__ int8_t g_c5[BSZ*256];
__device__ int8_t g_f0[BSZ*512];
__device__ int8_t g_f1[BSZ*512];

__device__ int8_t g_w0[64*36];
__device__ int8_t g_w1[64*592];
__device__ int8_t g_w2[128*592];
__device__ int8_t g_w3[128*1168];
__device__ int8_t g_w4[256*1168];
__device__ int8_t g_w5[256*2304];     // [oc][9][256] im2col order (gemm)
__device__ int8_t g_wf0[512*256];
__device__ int8_t g_wf1[512*512];
__device__ int8_t g_wf2[10*512];

__device__ float g_bns[6*256], g_bnm[6*256], g_bnb[6*256];
__device__ float g_fns[2*512], g_fnm[2*512], g_fnb[2*512];

// ---------------- helpers ----------------
__device__ __forceinline__ int8_t qtern(float y){
    float r = rintf(y);
    r = fminf(fmaxf(r, -1.f), 1.f);
    return (int8_t)r;
}

// exact ternary 2x2 avg+rint(half-even)+clip: +1 iff s>=3, -1 iff s<=-3
__device__ __forceinline__ int pq4(int x0,int x1,int x2,int x3){
    unsigned s = __vadd4(__vadd4((unsigned)x0,(unsigned)x1),
                         __vadd4((unsigned)x2,(unsigned)x3));
    return (int)((__vcmpges4(s, 0x03030303u) & 0x01010101u) | __vcmples4(s, 0xFDFDFDFDu));
}

__device__ __forceinline__ void mma_s8(int* c, int a0,int a1,int a2,int a3,int b0,int b1){
    asm volatile(
        "mma.sync.aligned.m16n8k32.row.col.s32.s8.s8.s32 "
        "{%0,%1,%2,%3},{%4,%5,%6,%7},{%8,%9},{%0,%1,%2,%3};"
        : "+r"(c[0]),"+r"(c[1]),"+r"(c[2]),"+r"(c[3])
        : "r"(a0),"r"(a1),"r"(a2),"r"(a3),"r"(b0),"r"(b1));
}

__device__ __forceinline__ void ldsm_x4(uint32_t addr, int& r0,int& r1,int& r2,int& r3){
    asm volatile("ldmatrix.sync.aligned.m8n8.x4.shared.b16 {%0,%1,%2,%3}, [%4];"
        : "=r"(r0),"=r"(r1),"=r"(r2),"=r"(r3) : "r"(addr));
}

__device__ __forceinline__ int8_t wq(float v){
    float r = rintf(v);
    r = fminf(fmaxf(r, -1.f), 1.f);
    return (int8_t)r;
}

__device__ __forceinline__ uint32_t smem_u32(const void* p){
    uint32_t a;
    asm("{ .reg .u64 t; cvta.to.shared.u64 t, %1; cvt.u32.u64 %0, t; }" : "=r"(a) : "l"(p));
    return a;
}

// ---------------- single merged prep kernel (weights + bn) ----------------
__device__ __forceinline__ void wq_conv(const float* __restrict__ src, int8_t* dst,
                                        int CI, int CIP, int KP, int idx){
    int c  = idx % CIP;
    int k  = (idx / CIP) % 9;
    int oc = idx / (9*CIP);
    int8_t q = 0;
    if (c < CI) q = wq(src[(size_t)(oc*CI + c)*9 + k]);
    dst[(size_t)oc*KP + k*CIP + c] = q;
}

__global__ void k_prep_all(const float* wc0,const float* wc1,const float* wc2,
                           const float* wc3,const float* wc4,const float* wc5,
                           const float* wf0,const float* wf1,const float* wf2,
                           const float* b0,const float* b1,const float* b2,
                           const float* b3,const float* b4,const float* b5,
                           const float* f0,const float* f1){
    int idx = blockIdx.x*256 + threadIdx.x;
    if (idx < 2304)  { wq_conv(wc0, g_w0, 3,  4,  36,  idx); return; }  idx -= 2304;
    if (idx < 36864) { wq_conv(wc1, g_w1, 64, 64, 592, idx); return; }  idx -= 36864;
    if (idx < 73728) { wq_conv(wc2, g_w2, 64, 64, 592, idx); return; }  idx -= 73728;
    if (idx < 147456){ wq_conv(wc3, g_w3, 128,128,1168,idx); return; }  idx -= 147456;
    if (idx < 294912){ wq_conv(wc4, g_w4, 128,128,1168,idx); return; }  idx -= 294912;
    if (idx < 589824){ wq_conv(wc5, g_w5, 256,256,2304,idx); return; }  idx -= 589824;
    if (idx < 131072){ g_wf0[idx] = wq(wf0[idx]); return; }             idx -= 131072;
    if (idx < 262144){ g_wf1[idx] = wq(wf1[idx]); return; }             idx -= 262144;
    if (idx < 5120)  { g_wf2[idx] = wq(wf2[idx]); return; }             idx -= 5120;
    if (idx < 1536){
        const float* srcs[6] = {b0,b1,b2,b3,b4,b5};
        const int    chs [6] = {64,64,128,128,256,256};
        int seg = idx >> 8, c = idx & 255;
        int C = chs[seg];
        if (c < C){
            const float* p = srcs[seg];
            g_bns[seg*256+c] = p[c] / sqrtf(p[3*C+c] + 1e-4f);
            g_bnm[seg*256+c] = p[2*C+c];
            g_bnb[seg*256+c] = p[C+c];
        }
        return;
    }
    idx -= 1536;
    if (idx < 1024){
        int k = idx >> 9, c = idx & 511;
        const float* p = k ? f1 : f0;
        g_fns[k*512+c] = p[c] / sqrtf(p[1536+c] + 1e-4f);
        g_fnm[k*512+c] = p[1024+c];
        g_fnb[k*512+c] = p[512+c];
    }
}

// ---------------- conv0: fused inquant + dp4a conv (4 pixels/thread) ----------------
__global__ void __launch_bounds__(256) k_conv0(
    const float* __restrict__ x, const int8_t* __restrict__ wt,
    const float* __restrict__ bs, const float* __restrict__ bm, const float* __restrict__ bb,
    int8_t* __restrict__ out)
{
    __shared__ int8_t s_w[64*36];
    __shared__ int    s_in[1024];
    const int tid = threadIdx.x;
    const int img = blockIdx.x;

    {
        const int4* src = (const int4*)wt;
        int4* dst = (int4*)s_w;
        for (int i = tid; i < 144; i += 256) dst[i] = src[i];
    }
    {
        const float* xb = x + (size_t)img*3072;
        for (int i = tid; i < 1024; i += 256){
            char4 r; float v;
            v = rintf(xb[i]     *128.f); v = fminf(fmaxf(v,-128.f),127.f); r.x = (signed char)v;
            v = rintf(xb[1024+i]*128.f); v = fminf(fmaxf(v,-128.f),127.f); r.y = (signed char)v;
            v = rintf(xb[2048+i]*128.f); v = fminf(fmaxf(v,-128.f),127.f); r.z = (signed char)v;
            r.w = 0;
            s_in[i] = *(int*)&r;
        }
    }
    __syncthreads();

    // 225 groups of 4 pixels x 4 ocg = 900 work items; weight LDS amortized x4
    for (int t = tid; t < 900; t += 256){
        int gp  = t % 225;
        int ocg = t / 225;
        const int p0 = gp*4;
        int pys[4], pxs[4];
        #pragma unroll
        for (int q=0;q<4;q++){ pys[q] = (p0+q)/30; pxs[q] = (p0+q)%30; }

        int acc[4][16];
        #pragma unroll
        for (int q=0;q<4;q++)
            #pragma unroll
            for (int j=0;j<16;j++) acc[q][j]=0;
        const int8_t* wb_ = s_w + ocg*16*36;

        #pragma unroll
        for (int ky=0; ky<3; ky++){
            #pragma unroll
            for (int kx=0; kx<3; kx++){
                const int kk = ky*3 + kx;
                int a[4];
                #pragma unroll
                for (int q=0;q<4;q++) a[q] = s_in[(pys[q]+ky)*32 + pxs[q]+kx];
                #pragma unroll
                for (int j=0;j<16;j++){
                    int w = *(const int*)(wb_ + (j*9 + kk)*4);
                    #pragma unroll
                    for (int q=0;q<4;q++) acc[q][j] = __dp4a(a[q], w, acc[q][j]);
                }
            }
        }
        #pragma unroll
        for (int q=0;q<4;q++){
            union { int8_t b[16]; int4 v; } o;
            #pragma unroll
            for (int j=0;j<16;j++){
                int oc = ocg*16 + j;
                float y = ((float)acc[q][j]*(1.0f/128.0f) - bm[oc]) * bs[oc] + bb[oc];
                o.b[j] = qtern(y);
            }
            *(int4*)(out + ((size_t)img*900 + p0+q)*64 + ocg*16) = o.v;
        }
    }
}

// ---------------- implicit-GEMM conv via ldmatrix + mma.sync ----------------
// 8 m-warps x 1 n-warp: each warp owns 16*AT rows and ALL 64 oc (NT=8).
// POOL: input is the pre-pool tensor [img][2*HIN][2*WIN][CIN]; staging applies
// the exact ternary 2x2 avg-pool while filling smem.
template<int CIN,int COUT,int OCT,int HIN,int WIN,int NIMG,int AT,bool POOL>
__global__ void __launch_bounds__(256) k_cmma(
    const int8_t* __restrict__ in, const int8_t* __restrict__ wt,
    const float* __restrict__ bs, const float* __restrict__ bm, const float* __restrict__ bb,
    int8_t* __restrict__ out)
{
    constexpr int HOUT = HIN-2, WOUT = WIN-2;
    constexpr int NPIX = HOUT*WOUT, INPIX = HIN*WIN;
    constexpr int K  = 9*CIN, KP = K+16, SA = CIN+16;
    constexpr int CH = K/32;
    constexpr int CPT = CIN/32;
    constexpr int NT = OCT/8;
    constexpr int NP = NT/2;
    constexpr int AW = NIMG*INPIX*SA;
    constexpr int MROW = 16*AT;
    constexpr int CTAROW = 8*MROW;
    constexpr int MT = (NIMG*NPIX + CTAROW-1)/CTAROW;

    extern __shared__ int8_t smem[];
    int8_t* s_a = smem;
    int8_t* s_w = smem + AW;

    const int tid  = threadIdx.x;
    const int img0 = blockIdx.x * NIMG;
    const int NI   = (BSZ - img0 < NIMG) ? (BSZ - img0) : NIMG;
    const int NROWSE = NI*NPIX;
    const int ocb  = blockIdx.y * OCT;
    const int lane = tid & 31;
    const int wm   = tid >> 5;

    {
        constexpr int RV = CIN/16;
        const int tot = NI*INPIX*RV;
        if (POOL){
            #pragma unroll 2
            for (int i = tid; i < tot; i += 256){
                int c16 = i % RV;
                int pix = i / RV;
                int im  = pix / INPIX;
                int pp  = pix - im*INPIX;
                int oy  = pp / WIN, ox = pp - oy*WIN;
                const int8_t* base = in
                    + ((size_t)(img0+im)*(4*INPIX) + (2*oy)*(2*WIN) + 2*ox)*CIN
                    + c16*16;
                int4 a0 = *(const int4*)base;
                int4 a1 = *(const int4*)(base + CIN);
                int4 a2 = *(const int4*)(base + 2*WIN*CIN);
                int4 a3 = *(const int4*)(base + 2*WIN*CIN + CIN);
                int4 o;
                o.x = pq4(a0.x,a1.x,a2.x,a3.x);
                o.y = pq4(a0.y,a1.y,a2.y,a3.y);
                o.z = pq4(a0.z,a1.z,a2.z,a3.z);
                o.w = pq4(a0.w,a1.w,a2.w,a3.w);
                ((int4*)s_a)[pix*(SA/16) + c16] = o;
            }
        } else {
            const int4* src = (const int4*)(in + (size_t)img0*INPIX*CIN);
            #pragma unroll 4
            for (int i = tid; i < tot; i += 256){
                int row = i / RV, j = i % RV;
                ((int4*)s_a)[row*(SA/16) + j] = src[i];
            }
        }
    }
    {
        const int4* src = (const int4*)(wt + (size_t)ocb*KP);
        int4* dst = (int4*)s_w;
        #pragma unroll 4
        for (int i = tid; i < OCT*KP/16; i += 256) dst[i] = src[i];
    }
    __syncthreads();

    const uint32_t s_a32 = smem_u32(s_a);
    const uint32_t s_w32 = smem_u32(s_w);

    uint32_t baddr[NP];
    #pragma unroll
    for (int p=0; p<NP; p++)
        baddr[p] = s_w32 + (uint32_t)((p*16 + ((lane>>4)<<3) + (lane&7))*KP
                                      + ((lane>>3)&1)*16);

    const int laneR = lane & 15;
    const int laneC = (lane >> 4) * 16;

    for (int mt = 0; mt < MT; mt++){
        const int rbase = mt*CTAROW + wm*MROW;

        uint32_t aA[AT];
        #pragma unroll
        for (int t=0; t<AT; t++){
            int r = rbase + 16*t + laneR;
            if (r >= NROWSE) r = 0;
            int im  = r / NPIX;
            int pix = r - im*NPIX;
            int py  = pix / WOUT;
            int px  = pix - py*WOUT;
            aA[t] = s_a32 + (uint32_t)((im*INPIX + py*WIN + px)*SA + laneC);
        }

        int acc[AT][NT][4];
        #pragma unroll
        for (int t=0;t<AT;t++)
            #pragma unroll
            for (int nt=0;nt<NT;nt++){ acc[t][nt][0]=acc[t][nt][1]=acc[t][nt][2]=acc[t][nt][3]=0; }

        #pragma unroll
        for (int ch = 0; ch < CH; ch++){
            const int kk = ch / CPT;
            const int cb = (ch % CPT)*32;
            const int aoff = ((kk/3)*WIN + (kk%3))*SA + cb;
            int a[AT][4];
            #pragma unroll
            for (int t=0;t<AT;t++)
                ldsm_x4(aA[t]+aoff, a[t][0],a[t][1],a[t][2],a[t][3]);
            int b[NT][2];
            #pragma unroll
            for (int p=0; p<NP; p++)
                ldsm_x4(baddr[p] + ch*32, b[2*p][0], b[2*p][1], b[2*p+1][0], b[2*p+1][1]);
            #pragma unroll
            for (int t=0;t<AT;t++)
                #pragma unroll
                for (int nt=0; nt<NT; nt++)
                    mma_s8(acc[t][nt], a[t][0],a[t][1],a[t][2],a[t][3], b[nt][0], b[nt][1]);
        }

        #pragma unroll
        for (int t=0; t<AT; t++){
            const int pa = rbase + 16*t + (lane>>2);
            const int pb = pa + 8;
            int ia = pa / NPIX, xa = pa - ia*NPIX;
            int ib = pb / NPIX, xb = pb - ib*NPIX;
            int8_t* oa = out + ((size_t)(img0+ia)*NPIX + xa)*COUT + ocb + (lane&3)*2;
            int8_t* ob = out + ((size_t)(img0+ib)*NPIX + xb)*COUT + ocb + (lane&3)*2;
            #pragma unroll
            for (int nt=0; nt<NT; nt++){
                const int col = ocb + nt*8 + (lane&3)*2;
                const float s0 = bs[col],   m0 = bm[col],   c0 = bb[col];
                const float s1 = bs[col+1], m1 = bm[col+1], c1 = bb[col+1];
                if (pa < NROWSE){
                    char2 o;
                    o.x = qtern(((float)acc[t][nt][0] - m0)*s0 + c0);
                    o.y = qtern(((float)acc[t][nt][1] - m1)*s1 + c1);
                    *(char2*)(oa + nt*8) = o;
                }
                if (pb < NROWSE){
                    char2 o;
                    o.x = qtern(((float)acc[t][nt][2] - m0)*s0 + c0);
                    o.y = qtern(((float)acc[t][nt][3] - m1)*s1 + c1);
                    *(char2*)(ob + nt*8) = o;
                }
            }
        }
    }
}

// ---------------- GEMM via ldmatrix + mma.sync (conv5/fc0/fc1) ----------------
template<int K,int N>
__global__ void __launch_bounds__(256) k_gemm(
    const int8_t* __restrict__ in, const int8_t* __restrict__ wt,
    const float* __restrict__ bs, const float* __restrict__ bm, const float* __restrict__ bb,
    int8_t* __restrict__ out)
{
    constexpr int KC = 256, SK = KC+16;
    extern __shared__ int8_t smem[];
    int8_t* s_a = smem;
    int8_t* s_b = smem + 64*SK;

    const int tid  = threadIdx.x;
    const int lane = tid & 31;
    const int warp = tid >> 5;
    const int wm   = warp & 1;
    const int wn   = warp >> 1;
    const int m0   = blockIdx.x * 64;
    const int n0   = blockIdx.y * 128;

    const uint32_t a32 = smem_u32(s_a);
    const uint32_t b32 = smem_u32(s_b);
    const int laneR = lane & 15;
    const int laneC = (lane >> 4) * 16;

    int acc[2][4][4];
    #pragma unroll
    for (int t=0;t<2;t++)
        #pragma unroll
        for (int nt=0;nt<4;nt++){ acc[t][nt][0]=acc[t][nt][1]=acc[t][nt][2]=acc[t][nt][3]=0; }

    for (int kc = 0; kc < K; kc += KC){
        if (kc) __syncthreads();
        for (int i = tid; i < 64*16; i += 256){
            int row = i >> 4, j = i & 15;
            ((int4*)s_a)[row*17 + j] = *(const int4*)(in + (size_t)(m0+row)*K + kc + j*16);
        }
        for (int i = tid; i < 128*16; i += 256){
            int row = i >> 4, j = i & 15;
            ((int4*)s_b)[row*17 + j] = *(const int4*)(wt + (size_t)(n0+row)*K + kc + j*16);
        }
        __syncthreads();

        #pragma unroll
        for (int ch = 0; ch < KC/32; ch++){
            int a0,a1,a2,a3,a4,a5,a6,a7;
            ldsm_x4(a32 + (wm*32 + laneR)*SK + laneC + ch*32,      a0,a1,a2,a3);
            ldsm_x4(a32 + (wm*32 + 16 + laneR)*SK + laneC + ch*32, a4,a5,a6,a7);
            int b[4][2];
            #pragma unroll
            for (int p=0; p<2; p++)
                ldsm_x4(b32 + (wn*32 + p*16 + ((lane>>4)<<3) + (lane&7))*SK
                            + ((lane>>3)&1)*16 + ch*32,
                        b[2*p][0], b[2*p][1], b[2*p+1][0], b[2*p+1][1]);
            #pragma unroll
            for (int nt=0; nt<4; nt++){
                mma_s8(acc[0][nt], a0,a1,a2,a3, b[nt][0], b[nt][1]);
                mma_s8(acc[1][nt], a4,a5,a6,a7, b[nt][0], b[nt][1]);
            }
        }
    }

    #pragma unroll
    for (int nt=0; nt<4; nt++){
        const int col = n0 + wn*32 + nt*8 + (lane&3)*2;
        const float s0 = bs[col],   m_ = bm[col],   b0_ = bb[col];
        const float s1 = bs[col+1], m1 = bm[col+1], b1_ = bb[col+1];
        #pragma unroll
        for (int t=0; t<2; t++){
            const int ra = m0 + wm*32 + 16*t + (lane>>2);
            char2 o;
            o.x = qtern(((float)acc[t][nt][0] - m_)*s0 + b0_);
            o.y = qtern(((float)acc[t][nt][1] - m1)*s1 + b1_);
            *(char2*)(out + (size_t)ra*N + col) = o;
            o.x = qtern(((float)acc[t][nt][2] - m_)*s0 + b0_);
            o.y = qtern(((float)acc[t][nt][3] - m1)*s1 + b1_);
            *(char2*)(out + (size_t)(ra+8)*N + col) = o;
        }
    }
}

// ---------------- last FC + TensorNorm ----------------
__global__ void k_fc_last(const int8_t* __restrict__ in, const int8_t* __restrict__ wt,
                          const float* __restrict__ tn, float* __restrict__ out){
    __shared__ int8_t s_a[512];
    int b = blockIdx.x, tid = threadIdx.x;
    for (int i = tid; i < 32; i += 256)
        ((int4*)s_a)[i] = ((const int4*)(in + (size_t)b*512))[i];
    __syncthreads();
    if (tid < 10){
        const int4* wr = (const int4*)(wt + (size_t)tid*512);
        int acc = 0;
        #pragma unroll 8
        for (int c=0;c<32;c++){
            int4 a = ((const int4*)s_a)[c];
            int4 w = wr[c];
            acc=__dp4a(a.x,w.x,acc); acc=__dp4a(a.y,w.y,acc);
            acc=__dp4a(a.z,w.z,acc); acc=__dp4a(a.w,w.w,acc);
        }
        float y = ((float)acc - tn[2]) / sqrtf(tn[3] + 1e-4f) * tn[0] + tn[1];
        out[b*10 + tid] = y;
    }
}

// ---------------- host ----------------
extern "C" void kernel_launch(void* const* d_in, const int* in_sizes, int n_in,
                              void* d_out, int out_size)
{
    const float *x=0, *wc[6]={0,0,0,0,0,0}, *bnc[6]={0,0,0,0,0,0};
    const float *wf[3]={0,0,0}, *bnf[2]={0,0}, *tn=0;
    int n256=0, n512=0, n1024=0, n2048=0;
    for (int i=0;i<n_in;i++){
        const float* p = (const float*)d_in[i];
        switch (in_sizes[i]){
            case 3145728: x = p; break;
            case 1728:    wc[0]=p; break;
            case 36864:   wc[1]=p; break;
            case 73728:   wc[2]=p; break;
            case 147456:  wc[3]=p; break;
            case 294912:  wc[4]=p; break;
            case 589824:  wc[5]=p; break;
            case 131072:  wf[0]=p; break;
            case 262144:  wf[1]=p; break;
            case 5120:    wf[2]=p; break;
            case 256:     if(n256 <2) bnc[0+n256++ ]=p; break;
            case 512:     if(n512 <2) bnc[2+n512++ ]=p; break;
            case 1024:    if(n1024<2) bnc[4+n1024++]=p; break;
            case 2048:    if(n2048<2) bnf[n2048++  ]=p; break;
            case 4:       tn = p; break;
            default: break;
        }
    }

    int8_t *c0,*c1,*c2,*c3,*c4,*c5,*f0,*f1;
    int8_t *w0,*w1,*w2,*w3,*w4,*w5,*wf0d,*wf1d,*wf2d;
    float *bns,*bnm,*bnb,*fns,*fnm,*fnb;
    cudaGetSymbolAddress((void**)&c0, g_c0);
    cudaGetSymbolAddress((void**)&c1, g_c1);
    cudaGetSymbolAddress((void**)&c2, g_c2);  cudaGetSymbolAddress((void**)&c3, g_c3);
    cudaGetSymbolAddress((void**)&c4, g_c4);
    cudaGetSymbolAddress((void**)&c5, g_c5);  cudaGetSymbolAddress((void**)&f0, g_f0);
    cudaGetSymbolAddress((void**)&f1, g_f1);
    cudaGetSymbolAddress((void**)&w0, g_w0);  cudaGetSymbolAddress((void**)&w1, g_w1);
    cudaGetSymbolAddress((void**)&w2, g_w2);  cudaGetSymbolAddress((void**)&w3, g_w3);
    cudaGetSymbolAddress((void**)&w4, g_w4);  cudaGetSymbolAddress((void**)&w5, g_w5);
    cudaGetSymbolAddress((void**)&wf0d, g_wf0); cudaGetSymbolAddress((void**)&wf1d, g_wf1);
    cudaGetSymbolAddress((void**)&wf2d, g_wf2);
    cudaGetSymbolAddress((void**)&bns, g_bns); cudaGetSymbolAddress((void**)&bnm, g_bnm);
    cudaGetSymbolAddress((void**)&bnb, g_bnb);
    cudaGetSymbolAddress((void**)&fns, g_fns); cudaGetSymbolAddress((void**)&fnm, g_fnm);
    cudaGetSymbolAddress((void**)&fnb, g_fnb);

    const int T = 256;
    const int GSM = 64*272 + 128*272;            // 52,224 gemm smem

    // launch 0: all weights + all bn (merged)
    k_prep_all<<<(1545984+T-1)/T, T>>>(wc[0],wc[1],wc[2],wc[3],wc[4],wc[5],
                                       wf[0],wf[1],wf[2],
                                       bnc[0],bnc[1],bnc[2],bnc[3],bnc[4],bnc[5],
                                       bnf[0],bnf[1]);
    // launch 1: conv0 (fused inquant, 4 px/thread)
    k_conv0<<<1024, T>>>(x, w0, bns, bnm, bnb, c0);
    // launch 2: conv1 — 8m x 1n, AT=2, NIMG=1 (110KB smem, 2 CTA/SM)
    {
        const int SM = 1*900*80 + 64*592;        // 109,888
        cudaFuncSetAttribute(k_cmma<64,64,64,30,30,1,2,false>,
                             cudaFuncAttributeMaxDynamicSharedMemorySize, SM);
        k_cmma<64,64,64,30,30,1,2,false><<<dim3(1024,1), T, SM>>>(c0, w1, bns+256, bnm+256, bnb+256, c1);
    }
    // launch 3: conv2 — NIMG=8, fused pool1 (reads c1 directly)
    {
        const int SM = 8*196*80 + 64*592;        // 163,328
        cudaFuncSetAttribute(k_cmma<64,128,64,14,14,8,2,true>,
                             cudaFuncAttributeMaxDynamicSharedMemorySize, SM);
        k_cmma<64,128,64,14,14,8,2,true><<<dim3(128,2), T, SM>>>(c1, w2, bns+512, bnm+512, bnb+512, c2);
    }
    // launch 4: conv3 — NIMG=5
    {
        const int SM = 5*144*144 + 64*1168;      // 178,432
        cudaFuncSetAttribute(k_cmma<128,128,64,12,12,5,2,false>,
                             cudaFuncAttributeMaxDynamicSharedMemorySize, SM);
        k_cmma<128,128,64,12,12,5,2,false><<<dim3(205,2), T, SM>>>(c2, w3, bns+768, bnm+768, bnb+768, c3);
    }
    // launch 5: conv4 — NIMG=28, fused pool3 (reads c3 directly)
    {
        const int SM = 28*25*144 + 64*1168;      // 175,552
        cudaFuncSetAttribute(k_cmma<128,256,64,5,5,28,2,true>,
                             cudaFuncAttributeMaxDynamicSharedMemorySize, SM);
        k_cmma<128,256,64,5,5,28,2,true><<<dim3(37,4), T, SM>>>(c3, w4, bns+1024, bnm+1024, bnb+1024, c4);
    }
    // launch 6: conv5 as GEMM (M=1024, N=256, K=2304)
    cudaFuncSetAttribute(k_gemm<2304,256>, cudaFuncAttributeMaxDynamicSharedMemorySize, GSM);
    k_gemm<2304,256><<<dim3(16,2), T, GSM>>>(c4, w5, bns+1280, bnm+1280, bnb+1280, c5);
    // launch 7: fc0 (K=256, N=512)
    cudaFuncSetAttribute(k_gemm<256,512>, cudaFuncAttributeMaxDynamicSharedMemorySize, GSM);
    k_gemm<256,512><<<dim3(16,4), T, GSM>>>(c5, wf0d, fns, fnm, fnb, f0);
    // launch 8: fc1 (K=512, N=512)
    cudaFuncSetAttribute(k_gemm<512,512>, cudaFuncAttributeMaxDynamicSharedMemorySize, GSM);
    k_gemm<512,512><<<dim3(16,4), T, GSM>>>(f0, wf1d, fns+512, fnm+512, fnb+512, f1);
    // launch 9: fc2 + TensorNorm
    k_fc_last<<<BSZ, T>>>(f1, wf2d, tn, (float*)d_out);
}

// round 16
// speedup vs baseline: 1.0740x; 1.0052x over previous
#include <cuda_runtime.h>
#include <cstdint>

#define BSZ 1024

// ---------------- static device buffers ----------------
__device__ int8_t g_c0[BSZ*30*30*64];
__device__ int8_t g_c1[BSZ*28*28*64];
__device__ int8_t g_c2[BSZ*12*12*128];
__device__ int8_t g_c3[BSZ*10*10*128];
__device__ int8_t g_c4[BSZ*3*3*256];
__device__ int8_t g_c5[BSZ*256];
__device__ int8_t g_f0[BSZ*512];
__device__ int8_t g_f1[BSZ*512];

__device__ int8_t g_w0[64*36];
__device__ int8_t g_w1[64*592];
__device__ int8_t g_w2[128*592];
__device__ int8_t g_w3[128*1168];
__device__ int8_t g_w4[256*1168];
__device__ int8_t g_w5[256*2304];     // [oc][9][256] im2col order (gemm)
__device__ int8_t g_wf0[512*256];
__device__ int8_t g_wf1[512*512];
__device__ int8_t g_wf2[10*512];

__device__ float g_bns[6*256], g_bnm[6*256], g_bnb[6*256];
__device__ float g_fns[2*512], g_fnm[2*512], g_fnb[2*512];

// ---------------- helpers ----------------
__device__ __forceinline__ int8_t qtern(float y){
    float r = rintf(y);
    r = fminf(fmaxf(r, -1.f), 1.f);
    return (int8_t)r;
}

// exact ternary 2x2 avg+rint(half-even)+clip: +1 iff s>=3, -1 iff s<=-3
__device__ __forceinline__ int pq4(int x0,int x1,int x2,int x3){
    unsigned s = __vadd4(__vadd4((unsigned)x0,(unsigned)x1),
                         __vadd4((unsigned)x2,(unsigned)x3));
    return (int)((__vcmpges4(s, 0x03030303u) & 0x01010101u) | __vcmples4(s, 0xFDFDFDFDu));
}

__device__ __forceinline__ void mma_s8(int* c, int a0,int a1,int a2,int a3,int b0,int b1){
    asm volatile(
        "mma.sync.aligned.m16n8k32.row.col.s32.s8.s8.s32 "
        "{%0,%1,%2,%3},{%4,%5,%6,%7},{%8,%9},{%0,%1,%2,%3};"
        : "+r"(c[0]),"+r"(c[1]),"+r"(c[2]),"+r"(c[3])
        : "r"(a0),"r"(a1),"r"(a2),"r"(a3),"r"(b0),"r"(b1));
}

__device__ __forceinline__ void ldsm_x4(uint32_t addr, int& r0,int& r1,int& r2,int& r3){
    asm volatile("ldmatrix.sync.aligned.m8n8.x4.shared.b16 {%0,%1,%2,%3}, [%4];"
        : "=r"(r0),"=r"(r1),"=r"(r2),"=r"(r3) : "r"(addr));
}

__device__ __forceinline__ int8_t wq(float v){
    float r = rintf(v);
    r = fminf(fmaxf(r, -1.f), 1.f);
    return (int8_t)r;
}

__device__ __forceinline__ uint32_t smem_u32(const void* p){
    uint32_t a;
    asm("{ .reg .u64 t; cvta.to.shared.u64 t, %1; cvt.u32.u64 %0, t; }" : "=r"(a) : "l"(p));
    return a;
}

// ---------------- single merged prep kernel (weights + bn) ----------------
__device__ __forceinline__ void wq_conv(const float* __restrict__ src, int8_t* dst,
                                        int CI, int CIP, int KP, int idx){
    int c  = idx % CIP;
    int k  = (idx / CIP) % 9;
    int oc = idx / (9*CIP);
    int8_t q = 0;
    if (c < CI) q = wq(src[(size_t)(oc*CI + c)*9 + k]);
    dst[(size_t)oc*KP + k*CIP + c] = q;
}

__global__ void k_prep_all(const float* wc0,const float* wc1,const float* wc2,
                           const float* wc3,const float* wc4,const float* wc5,
                           const float* wf0,const float* wf1,const float* wf2,
                           const float* b0,const float* b1,const float* b2,
                           const float* b3,const float* b4,const float* b5,
                           const float* f0,const float* f1){
    int idx = blockIdx.x*256 + threadIdx.x;
    if (idx < 2304)  { wq_conv(wc0, g_w0, 3,  4,  36,  idx); return; }  idx -= 2304;
    if (idx < 36864) { wq_conv(wc1, g_w1, 64, 64, 592, idx); return; }  idx -= 36864;
    if (idx < 73728) { wq_conv(wc2, g_w2, 64, 64, 592, idx); return; }  idx -= 73728;
    if (idx < 147456){ wq_conv(wc3, g_w3, 128,128,1168,idx); return; }  idx -= 147456;
    if (idx < 294912){ wq_conv(wc4, g_w4, 128,128,1168,idx); return; }  idx -= 294912;
    if (idx < 589824){ wq_conv(wc5, g_w5, 256,256,2304,idx); return; }  idx -= 589824;
    if (idx < 131072){ g_wf0[idx] = wq(wf0[idx]); return; }             idx -= 131072;
    if (idx < 262144){ g_wf1[idx] = wq(wf1[idx]); return; }             idx -= 262144;
    if (idx < 5120)  { g_wf2[idx] = wq(wf2[idx]); return; }             idx -= 5120;
    if (idx < 1536){
        const float* srcs[6] = {b0,b1,b2,b3,b4,b5};
        const int    chs [6] = {64,64,128,128,256,256};
        int seg = idx >> 8, c = idx & 255;
        int C = chs[seg];
        if (c < C){
            const float* p = srcs[seg];
            g_bns[seg*256+c] = p[c] / sqrtf(p[3*C+c] + 1e-4f);
            g_bnm[seg*256+c] = p[2*C+c];
            g_bnb[seg*256+c] = p[C+c];
        }
        return;
    }
    idx -= 1536;
    if (idx < 1024){
        int k = idx >> 9, c = idx & 511;
        const float* p = k ? f1 : f0;
        g_fns[k*512+c] = p[c] / sqrtf(p[1536+c] + 1e-4f);
        g_fnm[k*512+c] = p[1024+c];
        g_fnb[k*512+c] = p[512+c];
    }
}

// ---------------- conv0: fused inquant + dp4a conv (4 pixels/thread) ----------------
__global__ void __launch_bounds__(256) k_conv0(
    const float* __restrict__ x, const int8_t* __restrict__ wt,
    const float* __restrict__ bs, const float* __restrict__ bm, const float* __restrict__ bb,
    int8_t* __restrict__ out)
{
    __shared__ int8_t s_w[64*36];
    __shared__ int    s_in[1024];
    const int tid = threadIdx.x;
    const int img = blockIdx.x;

    {
        const int4* src = (const int4*)wt;
        int4* dst = (int4*)s_w;
        for (int i = tid; i < 144; i += 256) dst[i] = src[i];
    }
    {
        const float* xb = x + (size_t)img*3072;
        for (int i = tid; i < 1024; i += 256){
            char4 r; float v;
            v = rintf(xb[i]     *128.f); v = fminf(fmaxf(v,-128.f),127.f); r.x = (signed char)v;
            v = rintf(xb[1024+i]*128.f); v = fminf(fmaxf(v,-128.f),127.f); r.y = (signed char)v;
            v = rintf(xb[2048+i]*128.f); v = fminf(fmaxf(v,-128.f),127.f); r.z = (signed char)v;
            r.w = 0;
            s_in[i] = *(int*)&r;
        }
    }
    __syncthreads();

    for (int t = tid; t < 900; t += 256){
        int gp  = t % 225;
        int ocg = t / 225;
        const int p0 = gp*4;
        int pys[4], pxs[4];
        #pragma unroll
        for (int q=0;q<4;q++){ pys[q] = (p0+q)/30; pxs[q] = (p0+q)%30; }

        int acc[4][16];
        #pragma unroll
        for (int q=0;q<4;q++)
            #pragma unroll
            for (int j=0;j<16;j++) acc[q][j]=0;
        const int8_t* wb_ = s_w + ocg*16*36;

        #pragma unroll
        for (int ky=0; ky<3; ky++){
            #pragma unroll
            for (int kx=0; kx<3; kx++){
                const int kk = ky*3 + kx;
                int a[4];
                #pragma unroll
                for (int q=0;q<4;q++) a[q] = s_in[(pys[q]+ky)*32 + pxs[q]+kx];
                #pragma unroll
                for (int j=0;j<16;j++){
                    int w = *(const int*)(wb_ + (j*9 + kk)*4);
                    #pragma unroll
                    for (int q=0;q<4;q++) acc[q][j] = __dp4a(a[q], w, acc[q][j]);
                }
            }
        }
        #pragma unroll
        for (int q=0;q<4;q++){
            union { int8_t b[16]; int4 v; } o;
            #pragma unroll
            for (int j=0;j<16;j++){
                int oc = ocg*16 + j;
                float y = ((float)acc[q][j]*(1.0f/128.0f) - bm[oc]) * bs[oc] + bb[oc];
                o.b[j] = qtern(y);
            }
            *(int4*)(out + ((size_t)img*900 + p0+q)*64 + ocg*16) = o.v;
        }
    }
}

// ---------------- implicit-GEMM conv via ldmatrix + mma.sync ----------------
// 8 m-warps x 1 n-warp: each warp owns 16*AT rows and ALL OCT oc (NT=OCT/8).
// POOL: input is the pre-pool tensor; staging applies exact ternary 2x2 pool.
template<int CIN,int COUT,int OCT,int HIN,int WIN,int NIMG,int AT,bool POOL>
__global__ void __launch_bounds__(256) k_cmma(
    const int8_t* __restrict__ in, const int8_t* __restrict__ wt,
    const float* __restrict__ bs, const float* __restrict__ bm, const float* __restrict__ bb,
    int8_t* __restrict__ out)
{
    constexpr int HOUT = HIN-2, WOUT = WIN-2;
    constexpr int NPIX = HOUT*WOUT, INPIX = HIN*WIN;
    constexpr int K  = 9*CIN, KP = K+16, SA = CIN+16;
    constexpr int CH = K/32;
    constexpr int CPT = CIN/32;
    constexpr int NT = OCT/8;
    constexpr int NP = NT/2;
    constexpr int AW = NIMG*INPIX*SA;
    constexpr int MROW = 16*AT;
    constexpr int CTAROW = 8*MROW;
    constexpr int MT = (NIMG*NPIX + CTAROW-1)/CTAROW;

    extern __shared__ int8_t smem[];
    int8_t* s_a = smem;
    int8_t* s_w = smem + AW;

    const int tid  = threadIdx.x;
    const int img0 = blockIdx.x * NIMG;
    const int NI   = (BSZ - img0 < NIMG) ? (BSZ - img0) : NIMG;
    const int NROWSE = NI*NPIX;
    const int ocb  = blockIdx.y * OCT;
    const int lane = tid & 31;
    const int wm   = tid >> 5;

    {
        constexpr int RV = CIN/16;
        const int tot = NI*INPIX*RV;
        if (POOL){
            #pragma unroll 2
            for (int i = tid; i < tot; i += 256){
                int c16 = i % RV;
                int pix = i / RV;
                int im  = pix / INPIX;
                int pp  = pix - im*INPIX;
                int oy  = pp / WIN, ox = pp - oy*WIN;
                const int8_t* base = in
                    + ((size_t)(img0+im)*(4*INPIX) + (2*oy)*(2*WIN) + 2*ox)*CIN
                    + c16*16;
                int4 a0 = *(const int4*)base;
                int4 a1 = *(const int4*)(base + CIN);
                int4 a2 = *(const int4*)(base + 2*WIN*CIN);
                int4 a3 = *(const int4*)(base + 2*WIN*CIN + CIN);
                int4 o;
                o.x = pq4(a0.x,a1.x,a2.x,a3.x);
                o.y = pq4(a0.y,a1.y,a2.y,a3.y);
                o.z = pq4(a0.z,a1.z,a2.z,a3.z);
                o.w = pq4(a0.w,a1.w,a2.w,a3.w);
                ((int4*)s_a)[pix*(SA/16) + c16] = o;
            }
        } else {
            const int4* src = (const int4*)(in + (size_t)img0*INPIX*CIN);
            #pragma unroll 4
            for (int i = tid; i < tot; i += 256){
                int row = i / RV, j = i % RV;
                ((int4*)s_a)[row*(SA/16) + j] = src[i];
            }
        }
    }
    {
        const int4* src = (const int4*)(wt + (size_t)ocb*KP);
        int4* dst = (int4*)s_w;
        #pragma unroll 4
        for (int i = tid; i < OCT*KP/16; i += 256) dst[i] = src[i];
    }
    __syncthreads();

    const uint32_t s_a32 = smem_u32(s_a);
    const uint32_t s_w32 = smem_u32(s_w);

    uint32_t baddr[NP];
    #pragma unroll
    for (int p=0; p<NP; p++)
        baddr[p] = s_w32 + (uint32_t)((p*16 + ((lane>>4)<<3) + (lane&7))*KP
                                      + ((lane>>3)&1)*16);

    const int laneR = lane & 15;
    const int laneC = (lane >> 4) * 16;

    for (int mt = 0; mt < MT; mt++){
        const int rbase = mt*CTAROW + wm*MROW;

        uint32_t aA[AT];
        #pragma unroll
        for (int t=0; t<AT; t++){
            int r = rbase + 16*t + laneR;
            if (r >= NROWSE) r = 0;
            int im  = r / NPIX;
            int pix = r - im*NPIX;
            int py  = pix / WOUT;
            int px  = pix - py*WOUT;
            aA[t] = s_a32 + (uint32_t)((im*INPIX + py*WIN + px)*SA + laneC);
        }

        int acc[AT][NT][4];
        #pragma unroll
        for (int t=0;t<AT;t++)
            #pragma unroll
            for (int nt=0;nt<NT;nt++){ acc[t][nt][0]=acc[t][nt][1]=acc[t][nt][2]=acc[t][nt][3]=0; }

        #pragma unroll
        for (int ch = 0; ch < CH; ch++){
            const int kk = ch / CPT;
            const int cb = (ch % CPT)*32;
            const int aoff = ((kk/3)*WIN + (kk%3))*SA + cb;
            int a[AT][4];
            #pragma unroll
            for (int t=0;t<AT;t++)
                ldsm_x4(aA[t]+aoff, a[t][0],a[t][1],a[t][2],a[t][3]);
            #pragma unroll
            for (int p=0; p<NP; p++){
                int b0,b1,b2,b3;
                ldsm_x4(baddr[p] + ch*32, b0,b1,b2,b3);
                #pragma unroll
                for (int t=0;t<AT;t++){
                    mma_s8(acc[t][2*p],   a[t][0],a[t][1],a[t][2],a[t][3], b0,b1);
                    mma_s8(acc[t][2*p+1], a[t][0],a[t][1],a[t][2],a[t][3], b2,b3);
                }
            }
        }

        #pragma unroll
        for (int t=0; t<AT; t++){
            const int pa = rbase + 16*t + (lane>>2);
            const int pb = pa + 8;
            int ia = pa / NPIX, xa = pa - ia*NPIX;
            int ib = pb / NPIX, xb = pb - ib*NPIX;
            int8_t* oa = out + ((size_t)(img0+ia)*NPIX + xa)*COUT + ocb + (lane&3)*2;
            int8_t* ob = out + ((size_t)(img0+ib)*NPIX + xb)*COUT + ocb + (lane&3)*2;
            #pragma unroll
            for (int nt=0; nt<NT; nt++){
                const int col = ocb + nt*8 + (lane&3)*2;
                const float s0 = bs[col],   m0 = bm[col],   c0 = bb[col];
                const float s1 = bs[col+1], m1 = bm[col+1], c1 = bb[col+1];
                if (pa < NROWSE){
                    char2 o;
                    o.x = qtern(((float)acc[t][nt][0] - m0)*s0 + c0);
                    o.y = qtern(((float)acc[t][nt][1] - m1)*s1 + c1);
                    *(char2*)(oa + nt*8) = o;
                }
                if (pb < NROWSE){
                    char2 o;
                    o.x = qtern(((float)acc[t][nt][2] - m0)*s0 + c0);
                    o.y = qtern(((float)acc[t][nt][3] - m1)*s1 + c1);
                    *(char2*)(ob + nt*8) = o;
                }
            }
        }
    }
}

// ---------------- GEMM via ldmatrix + mma.sync (conv5/fc0/fc1) ----------------
template<int K,int N>
__global__ void __launch_bounds__(256) k_gemm(
    const int8_t* __restrict__ in, const int8_t* __restrict__ wt,
    const float* __restrict__ bs, const float* __restrict__ bm, const float* __restrict__ bb,
    int8_t* __restrict__ out)
{
    constexpr int KC = 256, SK = KC+16;
    extern __shared__ int8_t smem[];
    int8_t* s_a = smem;
    int8_t* s_b = smem + 64*SK;

    const int tid  = threadIdx.x;
    const int lane = tid & 31;
    const int warp = tid >> 5;
    const int wm   = warp & 1;
    const int wn   = warp >> 1;
    const int m0   = blockIdx.x * 64;
    const int n0   = blockIdx.y * 128;

    const uint32_t a32 = smem_u32(s_a);
    const uint32_t b32 = smem_u32(s_b);
    const int laneR = lane & 15;
    const int laneC = (lane >> 4) * 16;

    int acc[2][4][4];
    #pragma unroll
    for (int t=0;t<2;t++)
        #pragma unroll
        for (int nt=0;nt<4;nt++){ acc[t][nt][0]=acc[t][nt][1]=acc[t][nt][2]=acc[t][nt][3]=0; }

    for (int kc = 0; kc < K; kc += KC){
        if (kc) __syncthreads();
        for (int i = tid; i < 64*16; i += 256){
            int row = i >> 4, j = i & 15;
            ((int4*)s_a)[row*17 + j] = *(const int4*)(in + (size_t)(m0+row)*K + kc + j*16);
        }
        for (int i = tid; i < 128*16; i += 256){
            int row = i >> 4, j = i & 15;
            ((int4*)s_b)[row*17 + j] = *(const int4*)(wt + (size_t)(n0+row)*K + kc + j*16);
        }
        __syncthreads();

        #pragma unroll
        for (int ch = 0; ch < KC/32; ch++){
            int a0,a1,a2,a3,a4,a5,a6,a7;
            ldsm_x4(a32 + (wm*32 + laneR)*SK + laneC + ch*32,      a0,a1,a2,a3);
            ldsm_x4(a32 + (wm*32 + 16 + laneR)*SK + laneC + ch*32, a4,a5,a6,a7);
            int b[4][2];
            #pragma unroll
            for (int p=0; p<2; p++)
                ldsm_x4(b32 + (wn*32 + p*16 + ((lane>>4)<<3) + (lane&7))*SK
                            + ((lane>>3)&1)*16 + ch*32,
                        b[2*p][0], b[2*p][1], b[2*p+1][0], b[2*p+1][1]);
            #pragma unroll
            for (int nt=0; nt<4; nt++){
                mma_s8(acc[0][nt], a0,a1,a2,a3, b[nt][0], b[nt][1]);
                mma_s8(acc[1][nt], a4,a5,a6,a7, b[nt][0], b[nt][1]);
            }
        }
    }

    #pragma unroll
    for (int nt=0; nt<4; nt++){
        const int col = n0 + wn*32 + nt*8 + (lane&3)*2;
        const float s0 = bs[col],   m_ = bm[col],   b0_ = bb[col];
        const float s1 = bs[col+1], m1 = bm[col+1], b1_ = bb[col+1];
        #pragma unroll
        for (int t=0; t<2; t++){
            const int ra = m0 + wm*32 + 16*t + (lane>>2);
            char2 o;
            o.x = qtern(((float)acc[t][nt][0] - m_)*s0 + b0_);
            o.y = qtern(((float)acc[t][nt][1] - m1)*s1 + b1_);
            *(char2*)(out + (size_t)ra*N + col) = o;
            o.x = qtern(((float)acc[t][nt][2] - m_)*s0 + b0_);
            o.y = qtern(((float)acc[t][nt][3] - m1)*s1 + b1_);
            *(char2*)(out + (size_t)(ra+8)*N + col) = o;
        }
    }
}

// ---------------- last FC + TensorNorm ----------------
__global__ void k_fc_last(const int8_t* __restrict__ in, const int8_t* __restrict__ wt,
                          const float* __restrict__ tn, float* __restrict__ out){
    __shared__ int8_t s_a[512];
    int b = blockIdx.x, tid = threadIdx.x;
    for (int i = tid; i < 32; i += 256)
        ((int4*)s_a)[i] = ((const int4*)(in + (size_t)b*512))[i];
    __syncthreads();
    if (tid < 10){
        const int4* wr = (const int4*)(wt + (size_t)tid*512);
        int acc = 0;
        #pragma unroll 8
        for (int c=0;c<32;c++){
            int4 a = ((const int4*)s_a)[c];
            int4 w = wr[c];
            acc=__dp4a(a.x,w.x,acc); acc=__dp4a(a.y,w.y,acc);
            acc=__dp4a(a.z,w.z,acc); acc=__dp4a(a.w,w.w,acc);
        }
        float y = ((float)acc - tn[2]) / sqrtf(tn[3] + 1e-4f) * tn[0] + tn[1];
        out[b*10 + tid] = y;
    }
}

// ---------------- host ----------------
extern "C" void kernel_launch(void* const* d_in, const int* in_sizes, int n_in,
                              void* d_out, int out_size)
{
    const float *x=0, *wc[6]={0,0,0,0,0,0}, *bnc[6]={0,0,0,0,0,0};
    const float *wf[3]={0,0,0}, *bnf[2]={0,0}, *tn=0;
    int n256=0, n512=0, n1024=0, n2048=0;
    for (int i=0;i<n_in;i++){
        const float* p = (const float*)d_in[i];
        switch (in_sizes[i]){
            case 3145728: x = p; break;
            case 1728:    wc[0]=p; break;
            case 36864:   wc[1]=p; break;
            case 73728:   wc[2]=p; break;
            case 147456:  wc[3]=p; break;
            case 294912:  wc[4]=p; break;
            case 589824:  wc[5]=p; break;
            case 131072:  wf[0]=p; break;
            case 262144:  wf[1]=p; break;
            case 5120:    wf[2]=p; break;
            case 256:     if(n256 <2) bnc[0+n256++ ]=p; break;
            case 512:     if(n512 <2) bnc[2+n512++ ]=p; break;
            case 1024:    if(n1024<2) bnc[4+n1024++]=p; break;
            case 2048:    if(n2048<2) bnf[n2048++  ]=p; break;
            case 4:       tn = p; break;
            default: break;
        }
    }

    int8_t *c0,*c1,*c2,*c3,*c4,*c5,*f0,*f1;
    int8_t *w0,*w1,*w2,*w3,*w4,*w5,*wf0d,*wf1d,*wf2d;
    float *bns,*bnm,*bnb,*fns,*fnm,*fnb;
    cudaGetSymbolAddress((void**)&c0, g_c0);
    cudaGetSymbolAddress((void**)&c1, g_c1);
    cudaGetSymbolAddress((void**)&c2, g_c2);  cudaGetSymbolAddress((void**)&c3, g_c3);
    cudaGetSymbolAddress((void**)&c4, g_c4);
    cudaGetSymbolAddress((void**)&c5, g_c5);  cudaGetSymbolAddress((void**)&f0, g_f0);
    cudaGetSymbolAddress((void**)&f1, g_f1);
    cudaGetSymbolAddress((void**)&w0, g_w0);  cudaGetSymbolAddress((void**)&w1, g_w1);
    cudaGetSymbolAddress((void**)&w2, g_w2);  cudaGetSymbolAddress((void**)&w3, g_w3);
    cudaGetSymbolAddress((void**)&w4, g_w4);  cudaGetSymbolAddress((void**)&w5, g_w5);
    cudaGetSymbolAddress((void**)&wf0d, g_wf0); cudaGetSymbolAddress((void**)&wf1d, g_wf1);
    cudaGetSymbolAddress((void**)&wf2d, g_wf2);
    cudaGetSymbolAddress((void**)&bns, g_bns); cudaGetSymbolAddress((void**)&bnm, g_bnm);
    cudaGetSymbolAddress((void**)&bnb, g_bnb);
    cudaGetSymbolAddress((void**)&fns, g_fns); cudaGetSymbolAddress((void**)&fnm, g_fnm);
    cudaGetSymbolAddress((void**)&fnb, g_fnb);

    const int T = 256;
    const int GSM = 64*272 + 128*272;            // 52,224 gemm smem

    // launch 0: all weights + all bn (merged)
    k_prep_all<<<(1545984+T-1)/T, T>>>(wc[0],wc[1],wc[2],wc[3],wc[4],wc[5],
                                       wf[0],wf[1],wf[2],
                                       bnc[0],bnc[1],bnc[2],bnc[3],bnc[4],bnc[5],
                                       bnf[0],bnf[1]);
    // launch 1: conv0 (fused inquant, 4 px/thread)
    k_conv0<<<1024, T>>>(x, w0, bns, bnm, bnb, c0);
    // launch 2: conv1 — OCT=64, AT=2, NIMG=1 (110KB smem, 2 CTA/SM)
    {
        const int SM = 1*900*80 + 64*592;        // 109,888
        cudaFuncSetAttribute(k_cmma<64,64,64,30,30,1,2,false>,
                             cudaFuncAttributeMaxDynamicSharedMemorySize, SM);
        k_cmma<64,64,64,30,30,1,2,false><<<dim3(1024,1), T, SM>>>(c0, w1, bns+256, bnm+256, bnb+256, c1);
    }
    // launch 3: conv2 — OCT=128 (full COUT), NIMG=8, fused pool1, ONE wave of 128 CTAs
    {
        const int SM = 8*196*80 + 128*592;       // 201,216
        cudaFuncSetAttribute(k_cmma<64,128,128,14,14,8,2,true>,
                             cudaFuncAttributeMaxDynamicSharedMemorySize, SM);
        k_cmma<64,128,128,14,14,8,2,true><<<dim3(128,1), T, SM>>>(c1, w2, bns+512, bnm+512, bnb+512, c2);
    }
    // launch 4: conv3 — NIMG=5
    {
        const int SM = 5*144*144 + 64*1168;      // 178,432
        cudaFuncSetAttribute(k_cmma<128,128,64,12,12,5,2,false>,
                             cudaFuncAttributeMaxDynamicSharedMemorySize, SM);
        k_cmma<128,128,64,12,12,5,2,false><<<dim3(205,2), T, SM>>>(c2, w3, bns+768, bnm+768, bnb+768, c3);
    }
    // launch 5: conv4 — NIMG=28, fused pool3 (148 CTAs = 1 wave)
    {
        const int SM = 28*25*144 + 64*1168;      // 175,552
        cudaFuncSetAttribute(k_cmma<128,256,64,5,5,28,2,true>,
                             cudaFuncAttributeMaxDynamicSharedMemorySize, SM);
        k_cmma<128,256,64,5,5,28,2,true><<<dim3(37,4), T, SM>>>(c3, w4, bns+1024, bnm+1024, bnb+1024, c4);
    }
    // launch 6: conv5 as GEMM (M=1024, N=256, K=2304)
    cudaFuncSetAttribute(k_gemm<2304,256>, cudaFuncAttributeMaxDynamicSharedMemorySize, GSM);
    k_gemm<2304,256><<<dim3(16,2), T, GSM>>>(c4, w5, bns+1280, bnm+1280, bnb+1280, c5);
    // launch 7: fc0 (K=256, N=512)
    cudaFuncSetAttribute(k_gemm<256,512>, cudaFuncAttributeMaxDynamicSharedMemorySize, GSM);
    k_gemm<256,512><<<dim3(16,4), T, GSM>>>(c5, wf0d, fns, fnm, fnb, f0);
    // launch 8: fc1 (K=512, N=512)
    cudaFuncSetAttribute(k_gemm<512,512>, cudaFuncAttributeMaxDynamicSharedMemorySize, GSM);
    k_gemm<512,512><<<dim3(16,4), T, GSM>>>(f0, wf1d, fns+512, fnm+512, fnb+512, f1);
    // launch 9: fc2 + TensorNorm
    k_fc_last<<<BSZ, T>>>(f1, wf2d, tn, (float*)d_out);
}

// round 17
// speedup vs baseline: 1.0844x; 1.0097x over previous
#include <cuda_runtime.h>
#include <cstdint>

#define BSZ 1024

// ---------------- static device buffers ----------------
__device__ int8_t g_c0[BSZ*30*30*64];
__device__ int8_t g_c1[BSZ*28*28*64];
__device__ int8_t g_c2[BSZ*12*12*128];
__device__ int8_t g_c3[BSZ*10*10*128];
__device__ int8_t g_c4[BSZ*3*3*256];
__device__ int8_t g_c5[BSZ*256];
__device__ int8_t g_f0[BSZ*512];
__device__ int8_t g_f1[BSZ*512];

__device__ int8_t g_w0[64*36];
__device__ int8_t g_w1[64*592];
__device__ int8_t g_w2[128*592];
__device__ int8_t g_w3[128*1168];
__device__ int8_t g_w4[256*1168];
__device__ int8_t g_w5[256*2304];     // [oc][9][256] im2col order (gemm)
__device__ int8_t g_wf0[512*256];
__device__ int8_t g_wf1[512*512];
__device__ int8_t g_wf2[10*512];

__device__ float g_bns[6*256], g_bnm[6*256], g_bnb[6*256];
__device__ float g_fns[2*512], g_fnm[2*512], g_fnb[2*512];

// ---------------- helpers ----------------
__device__ __forceinline__ int8_t qtern(float y){
    float r = rintf(y);
    r = fminf(fmaxf(r, -1.f), 1.f);
    return (int8_t)r;
}

// exact ternary 2x2 avg+rint(half-even)+clip: +1 iff s>=3, -1 iff s<=-3
__device__ __forceinline__ int pq4(int x0,int x1,int x2,int x3){
    unsigned s = __vadd4(__vadd4((unsigned)x0,(unsigned)x1),
                         __vadd4((unsigned)x2,(unsigned)x3));
    return (int)((__vcmpges4(s, 0x03030303u) & 0x01010101u) | __vcmples4(s, 0xFDFDFDFDu));
}

__device__ __forceinline__ void mma_s8(int* c, int a0,int a1,int a2,int a3,int b0,int b1){
    asm volatile(
        "mma.sync.aligned.m16n8k32.row.col.s32.s8.s8.s32 "
        "{%0,%1,%2,%3},{%4,%5,%6,%7},{%8,%9},{%0,%1,%2,%3};"
        : "+r"(c[0]),"+r"(c[1]),"+r"(c[2]),"+r"(c[3])
        : "r"(a0),"r"(a1),"r"(a2),"r"(a3),"r"(b0),"r"(b1));
}

__device__ __forceinline__ void ldsm_x4(uint32_t addr, int& r0,int& r1,int& r2,int& r3){
    asm volatile("ldmatrix.sync.aligned.m8n8.x4.shared.b16 {%0,%1,%2,%3}, [%4];"
        : "=r"(r0),"=r"(r1),"=r"(r2),"=r"(r3) : "r"(addr));
}

__device__ __forceinline__ int8_t wq(float v){
    float r = rintf(v);
    r = fminf(fmaxf(r, -1.f), 1.f);
    return (int8_t)r;
}

__device__ __forceinline__ uint32_t smem_u32(const void* p){
    uint32_t a;
    asm("{ .reg .u64 t; cvta.to.shared.u64 t, %1; cvt.u32.u64 %0, t; }" : "=r"(a) : "l"(p));
    return a;
}

// ---------------- single merged prep kernel (weights + bn) ----------------
__device__ __forceinline__ void wq_conv(const float* __restrict__ src, int8_t* dst,
                                        int CI, int CIP, int KP, int idx){
    int c  = idx % CIP;
    int k  = (idx / CIP) % 9;
    int oc = idx / (9*CIP);
    int8_t q = 0;
    if (c < CI) q = wq(src[(size_t)(oc*CI + c)*9 + k]);
    dst[(size_t)oc*KP + k*CIP + c] = q;
}

__global__ void k_prep_all(const float* wc0,const float* wc1,const float* wc2,
                           const float* wc3,const float* wc4,const float* wc5,
                           const float* wf0,const float* wf1,const float* wf2,
                           const float* b0,const float* b1,const float* b2,
                           const float* b3,const float* b4,const float* b5,
                           const float* f0,const float* f1){
    int idx = blockIdx.x*256 + threadIdx.x;
    if (idx < 2304)  { wq_conv(wc0, g_w0, 3,  4,  36,  idx); return; }  idx -= 2304;
    if (idx < 36864) { wq_conv(wc1, g_w1, 64, 64, 592, idx); return; }  idx -= 36864;
    if (idx < 73728) { wq_conv(wc2, g_w2, 64, 64, 592, idx); return; }  idx -= 73728;
    if (idx < 147456){ wq_conv(wc3, g_w3, 128,128,1168,idx); return; }  idx -= 147456;
    if (idx < 294912){ wq_conv(wc4, g_w4, 128,128,1168,idx); return; }  idx -= 294912;
    if (idx < 589824){ wq_conv(wc5, g_w5, 256,256,2304,idx); return; }  idx -= 589824;
    if (idx < 131072){ g_wf0[idx] = wq(wf0[idx]); return; }             idx -= 131072;
    if (idx < 262144){ g_wf1[idx] = wq(wf1[idx]); return; }             idx -= 262144;
    if (idx < 5120)  { g_wf2[idx] = wq(wf2[idx]); return; }             idx -= 5120;
    if (idx < 1536){
        const float* srcs[6] = {b0,b1,b2,b3,b4,b5};
        const int    chs [6] = {64,64,128,128,256,256};
        int seg = idx >> 8, c = idx & 255;
        int C = chs[seg];
        if (c < C){
            const float* p = srcs[seg];
            g_bns[seg*256+c] = p[c] / sqrtf(p[3*C+c] + 1e-4f);
            g_bnm[seg*256+c] = p[2*C+c];
            g_bnb[seg*256+c] = p[C+c];
        }
        return;
    }
    idx -= 1536;
    if (idx < 1024){
        int k = idx >> 9, c = idx & 511;
        const float* p = k ? f1 : f0;
        g_fns[k*512+c] = p[c] / sqrtf(p[1536+c] + 1e-4f);
        g_fnm[k*512+c] = p[1024+c];
        g_fnb[k*512+c] = p[512+c];
    }
}

// ---------------- conv0: fused inquant + dp4a conv (4 pixels/thread) ----------------
__global__ void __launch_bounds__(256) k_conv0(
    const float* __restrict__ x, const int8_t* __restrict__ wt,
    const float* __restrict__ bs, const float* __restrict__ bm, const float* __restrict__ bb,
    int8_t* __restrict__ out)
{
    __shared__ int8_t s_w[64*36];
    __shared__ int    s_in[1024];
    const int tid = threadIdx.x;
    const int img = blockIdx.x;

    {
        const int4* src = (const int4*)wt;
        int4* dst = (int4*)s_w;
        for (int i = tid; i < 144; i += 256) dst[i] = src[i];
    }
    {
        const float* xb = x + (size_t)img*3072;
        for (int i = tid; i < 1024; i += 256){
            char4 r; float v;
            v = rintf(xb[i]     *128.f); v = fminf(fmaxf(v,-128.f),127.f); r.x = (signed char)v;
            v = rintf(xb[1024+i]*128.f); v = fminf(fmaxf(v,-128.f),127.f); r.y = (signed char)v;
            v = rintf(xb[2048+i]*128.f); v = fminf(fmaxf(v,-128.f),127.f); r.z = (signed char)v;
            r.w = 0;
            s_in[i] = *(int*)&r;
        }
    }
    __syncthreads();

    for (int t = tid; t < 900; t += 256){
        int gp  = t % 225;
        int ocg = t / 225;
        const int p0 = gp*4;
        int pys[4], pxs[4];
        #pragma unroll
        for (int q=0;q<4;q++){ pys[q] = (p0+q)/30; pxs[q] = (p0+q)%30; }

        int acc[4][16];
        #pragma unroll
        for (int q=0;q<4;q++)
            #pragma unroll
            for (int j=0;j<16;j++) acc[q][j]=0;
        const int8_t* wb_ = s_w + ocg*16*36;

        #pragma unroll
        for (int ky=0; ky<3; ky++){
            #pragma unroll
            for (int kx=0; kx<3; kx++){
                const int kk = ky*3 + kx;
                int a[4];
                #pragma unroll
                for (int q=0;q<4;q++) a[q] = s_in[(pys[q]+ky)*32 + pxs[q]+kx];
                #pragma unroll
                for (int j=0;j<16;j++){
                    int w = *(const int*)(wb_ + (j*9 + kk)*4);
                    #pragma unroll
                    for (int q=0;q<4;q++) acc[q][j] = __dp4a(a[q], w, acc[q][j]);
                }
            }
        }
        #pragma unroll
        for (int q=0;q<4;q++){
            union { int8_t b[16]; int4 v; } o;
            #pragma unroll
            for (int j=0;j<16;j++){
                int oc = ocg*16 + j;
                float y = ((float)acc[q][j]*(1.0f/128.0f) - bm[oc]) * bs[oc] + bb[oc];
                o.b[j] = qtern(y);
            }
            *(int4*)(out + ((size_t)img*900 + p0+q)*64 + ocg*16) = o.v;
        }
    }
}

// ---------------- implicit-GEMM conv via ldmatrix + mma.sync ----------------
// 8 m-warps x 1 n-warp: each warp owns 16*AT rows and ALL OCT oc (NT=OCT/8).
// POOL: input is the pre-pool tensor; staging applies exact ternary 2x2 pool.
template<int CIN,int COUT,int OCT,int HIN,int WIN,int NIMG,int AT,bool POOL>
__global__ void __launch_bounds__(256) k_cmma(
    const int8_t* __restrict__ in, const int8_t* __restrict__ wt,
    const float* __restrict__ bs, const float* __restrict__ bm, const float* __restrict__ bb,
    int8_t* __restrict__ out)
{
    constexpr int HOUT = HIN-2, WOUT = WIN-2;
    constexpr int NPIX = HOUT*WOUT, INPIX = HIN*WIN;
    constexpr int K  = 9*CIN, KP = K+16, SA = CIN+16;
    constexpr int CH = K/32;
    constexpr int CPT = CIN/32;
    constexpr int NT = OCT/8;
    constexpr int NP = NT/2;
    constexpr int AW = NIMG*INPIX*SA;
    constexpr int MROW = 16*AT;
    constexpr int CTAROW = 8*MROW;
    constexpr int MT = (NIMG*NPIX + CTAROW-1)/CTAROW;

    extern __shared__ int8_t smem[];
    int8_t* s_a = smem;
    int8_t* s_w = smem + AW;

    const int tid  = threadIdx.x;
    const int img0 = blockIdx.x * NIMG;
    const int NI   = (BSZ - img0 < NIMG) ? (BSZ - img0) : NIMG;
    const int NROWSE = NI*NPIX;
    const int ocb  = blockIdx.y * OCT;
    const int lane = tid & 31;
    const int wm   = tid >> 5;

    {
        constexpr int RV = CIN/16;
        const int tot = NI*INPIX*RV;
        if (POOL){
            #pragma unroll 2
            for (int i = tid; i < tot; i += 256){
                int c16 = i % RV;
                int pix = i / RV;
                int im  = pix / INPIX;
                int pp  = pix - im*INPIX;
                int oy  = pp / WIN, ox = pp - oy*WIN;
                const int8_t* base = in
                    + ((size_t)(img0+im)*(4*INPIX) + (2*oy)*(2*WIN) + 2*ox)*CIN
                    + c16*16;
                int4 a0 = *(const int4*)base;
                int4 a1 = *(const int4*)(base + CIN);
                int4 a2 = *(const int4*)(base + 2*WIN*CIN);
                int4 a3 = *(const int4*)(base + 2*WIN*CIN + CIN);
                int4 o;
                o.x = pq4(a0.x,a1.x,a2.x,a3.x);
                o.y = pq4(a0.y,a1.y,a2.y,a3.y);
                o.z = pq4(a0.z,a1.z,a2.z,a3.z);
                o.w = pq4(a0.w,a1.w,a2.w,a3.w);
                ((int4*)s_a)[pix*(SA/16) + c16] = o;
            }
        } else {
            const int4* src = (const int4*)(in + (size_t)img0*INPIX*CIN);
            #pragma unroll 4
            for (int i = tid; i < tot; i += 256){
                int row = i / RV, j = i % RV;
                ((int4*)s_a)[row*(SA/16) + j] = src[i];
            }
        }
    }
    {
        const int4* src = (const int4*)(wt + (size_t)ocb*KP);
        int4* dst = (int4*)s_w;
        #pragma unroll 4
        for (int i = tid; i < OCT*KP/16; i += 256) dst[i] = src[i];
    }
    __syncthreads();

    const uint32_t s_a32 = smem_u32(s_a);
    const uint32_t s_w32 = smem_u32(s_w);

    uint32_t baddr[NP];
    #pragma unroll
    for (int p=0; p<NP; p++)
        baddr[p] = s_w32 + (uint32_t)((p*16 + ((lane>>4)<<3) + (lane&7))*KP
                                      + ((lane>>3)&1)*16);

    const int laneR = lane & 15;
    const int laneC = (lane >> 4) * 16;

    for (int mt = 0; mt < MT; mt++){
        const int rbase = mt*CTAROW + wm*MROW;

        uint32_t aA[AT];
        #pragma unroll
        for (int t=0; t<AT; t++){
            int r = rbase + 16*t + laneR;
            if (r >= NROWSE) r = 0;
            int im  = r / NPIX;
            int pix = r - im*NPIX;
            int py  = pix / WOUT;
            int px  = pix - py*WOUT;
            aA[t] = s_a32 + (uint32_t)((im*INPIX + py*WIN + px)*SA + laneC);
        }

        int acc[AT][NT][4];
        #pragma unroll
        for (int t=0;t<AT;t++)
            #pragma unroll
            for (int nt=0;nt<NT;nt++){ acc[t][nt][0]=acc[t][nt][1]=acc[t][nt][2]=acc[t][nt][3]=0; }

        #pragma unroll
        for (int ch = 0; ch < CH; ch++){
            const int kk = ch / CPT;
            const int cb = (ch % CPT)*32;
            const int aoff = ((kk/3)*WIN + (kk%3))*SA + cb;
            int a[AT][4];
            #pragma unroll
            for (int t=0;t<AT;t++)
                ldsm_x4(aA[t]+aoff, a[t][0],a[t][1],a[t][2],a[t][3]);
            #pragma unroll
            for (int p=0; p<NP; p++){
                int b0,b1,b2,b3;
                ldsm_x4(baddr[p] + ch*32, b0,b1,b2,b3);
                #pragma unroll
                for (int t=0;t<AT;t++){
                    mma_s8(acc[t][2*p],   a[t][0],a[t][1],a[t][2],a[t][3], b0,b1);
                    mma_s8(acc[t][2*p+1], a[t][0],a[t][1],a[t][2],a[t][3], b2,b3);
                }
            }
        }

        #pragma unroll
        for (int t=0; t<AT; t++){
            const int pa = rbase + 16*t + (lane>>2);
            const int pb = pa + 8;
            int ia = pa / NPIX, xa = pa - ia*NPIX;
            int ib = pb / NPIX, xb = pb - ib*NPIX;
            int8_t* oa = out + ((size_t)(img0+ia)*NPIX + xa)*COUT + ocb + (lane&3)*2;
            int8_t* ob = out + ((size_t)(img0+ib)*NPIX + xb)*COUT + ocb + (lane&3)*2;
            #pragma unroll
            for (int nt=0; nt<NT; nt++){
                const int col = ocb + nt*8 + (lane&3)*2;
                const float s0 = bs[col],   m0 = bm[col],   c0 = bb[col];
                const float s1 = bs[col+1], m1 = bm[col+1], c1 = bb[col+1];
                if (pa < NROWSE){
                    char2 o;
                    o.x = qtern(((float)acc[t][nt][0] - m0)*s0 + c0);
                    o.y = qtern(((float)acc[t][nt][1] - m1)*s1 + c1);
                    *(char2*)(oa + nt*8) = o;
                }
                if (pb < NROWSE){
                    char2 o;
                    o.x = qtern(((float)acc[t][nt][2] - m0)*s0 + c0);
                    o.y = qtern(((float)acc[t][nt][3] - m1)*s1 + c1);
                    *(char2*)(ob + nt*8) = o;
                }
            }
        }
    }
}

// ---------------- GEMM via ldmatrix + mma.sync (conv5/fc0/fc1) ----------------
template<int K,int N>
__global__ void __launch_bounds__(256) k_gemm(
    const int8_t* __restrict__ in, const int8_t* __restrict__ wt,
    const float* __restrict__ bs, const float* __restrict__ bm, const float* __restrict__ bb,
    int8_t* __restrict__ out)
{
    constexpr int KC = 256, SK = KC+16;
    extern __shared__ int8_t smem[];
    int8_t* s_a = smem;
    int8_t* s_b = smem + 64*SK;

    const int tid  = threadIdx.x;
    const int lane = tid & 31;
    const int warp = tid >> 5;
    const int wm   = warp & 1;
    const int wn   = warp >> 1;
    const int m0   = blockIdx.x * 64;
    const int n0   = blockIdx.y * 128;

    const uint32_t a32 = smem_u32(s_a);
    const uint32_t b32 = smem_u32(s_b);
    const int laneR = lane & 15;
    const int laneC = (lane >> 4) * 16;

    int acc[2][4][4];
    #pragma unroll
    for (int t=0;t<2;t++)
        #pragma unroll
        for (int nt=0;nt<4;nt++){ acc[t][nt][0]=acc[t][nt][1]=acc[t][nt][2]=acc[t][nt][3]=0; }

    for (int kc = 0; kc < K; kc += KC){
        if (kc) __syncthreads();
        for (int i = tid; i < 64*16; i += 256){
            int row = i >> 4, j = i & 15;
            ((int4*)s_a)[row*17 + j] = *(const int4*)(in + (size_t)(m0+row)*K + kc + j*16);
        }
        for (int i = tid; i < 128*16; i += 256){
            int row = i >> 4, j = i & 15;
            ((int4*)s_b)[row*17 + j] = *(const int4*)(wt + (size_t)(n0+row)*K + kc + j*16);
        }
        __syncthreads();

        #pragma unroll
        for (int ch = 0; ch < KC/32; ch++){
            int a0,a1,a2,a3,a4,a5,a6,a7;
            ldsm_x4(a32 + (wm*32 + laneR)*SK + laneC + ch*32,      a0,a1,a2,a3);
            ldsm_x4(a32 + (wm*32 + 16 + laneR)*SK + laneC + ch*32, a4,a5,a6,a7);
            int b[4][2];
            #pragma unroll
            for (int p=0; p<2; p++)
                ldsm_x4(b32 + (wn*32 + p*16 + ((lane>>4)<<3) + (lane&7))*SK
                            + ((lane>>3)&1)*16 + ch*32,
                        b[2*p][0], b[2*p][1], b[2*p+1][0], b[2*p+1][1]);
            #pragma unroll
            for (int nt=0; nt<4; nt++){
                mma_s8(acc[0][nt], a0,a1,a2,a3, b[nt][0], b[nt][1]);
                mma_s8(acc[1][nt], a4,a5,a6,a7, b[nt][0], b[nt][1]);
            }
        }
    }

    #pragma unroll
    for (int nt=0; nt<4; nt++){
        const int col = n0 + wn*32 + nt*8 + (lane&3)*2;
        const float s0 = bs[col],   m_ = bm[col],   b0_ = bb[col];
        const float s1 = bs[col+1], m1 = bm[col+1], b1_ = bb[col+1];
        #pragma unroll
        for (int t=0; t<2; t++){
            const int ra = m0 + wm*32 + 16*t + (lane>>2);
            char2 o;
            o.x = qtern(((float)acc[t][nt][0] - m_)*s0 + b0_);
            o.y = qtern(((float)acc[t][nt][1] - m1)*s1 + b1_);
            *(char2*)(out + (size_t)ra*N + col) = o;
            o.x = qtern(((float)acc[t][nt][2] - m_)*s0 + b0_);
            o.y = qtern(((float)acc[t][nt][3] - m1)*s1 + b1_);
            *(char2*)(out + (size_t)(ra+8)*N + col) = o;
        }
    }
}

// ---------------- last FC + TensorNorm ----------------
__global__ void k_fc_last(const int8_t* __restrict__ in, const int8_t* __restrict__ wt,
                          const float* __restrict__ tn, float* __restrict__ out){
    __shared__ int8_t s_a[512];
    int b = blockIdx.x, tid = threadIdx.x;
    for (int i = tid; i < 32; i += 256)
        ((int4*)s_a)[i] = ((const int4*)(in + (size_t)b*512))[i];
    __syncthreads();
    if (tid < 10){
        const int4* wr = (const int4*)(wt + (size_t)tid*512);
        int acc = 0;
        #pragma unroll 8
        for (int c=0;c<32;c++){
            int4 a = ((const int4*)s_a)[c];
            int4 w = wr[c];
            acc=__dp4a(a.x,w.x,acc); acc=__dp4a(a.y,w.y,acc);
            acc=__dp4a(a.z,w.z,acc); acc=__dp4a(a.w,w.w,acc);
        }
        float y = ((float)acc - tn[2]) / sqrtf(tn[3] + 1e-4f) * tn[0] + tn[1];
        out[b*10 + tid] = y;
    }
}

// ---------------- host ----------------
extern "C" void kernel_launch(void* const* d_in, const int* in_sizes, int n_in,
                              void* d_out, int out_size)
{
    const float *x=0, *wc[6]={0,0,0,0,0,0}, *bnc[6]={0,0,0,0,0,0};
    const float *wf[3]={0,0,0}, *bnf[2]={0,0}, *tn=0;
    int n256=0, n512=0, n1024=0, n2048=0;
    for (int i=0;i<n_in;i++){
        const float* p = (const float*)d_in[i];
        switch (in_sizes[i]){
            case 3145728: x = p; break;
            case 1728:    wc[0]=p; break;
            case 36864:   wc[1]=p; break;
            case 73728:   wc[2]=p; break;
            case 147456:  wc[3]=p; break;
            case 294912:  wc[4]=p; break;
            case 589824:  wc[5]=p; break;
            case 131072:  wf[0]=p; break;
            case 262144:  wf[1]=p; break;
            case 5120:    wf[2]=p; break;
            case 256:     if(n256 <2) bnc[0+n256++ ]=p; break;
            case 512:     if(n512 <2) bnc[2+n512++ ]=p; break;
            case 1024:    if(n1024<2) bnc[4+n1024++]=p; break;
            case 2048:    if(n2048<2) bnf[n2048++  ]=p; break;
            case 4:       tn = p; break;
            default: break;
        }
    }

    int8_t *c0,*c1,*c2,*c3,*c4,*c5,*f0,*f1;
    int8_t *w0,*w1,*w2,*w3,*w4,*w5,*wf0d,*wf1d,*wf2d;
    float *bns,*bnm,*bnb,*fns,*fnm,*fnb;
    cudaGetSymbolAddress((void**)&c0, g_c0);
    cudaGetSymbolAddress((void**)&c1, g_c1);
    cudaGetSymbolAddress((void**)&c2, g_c2);  cudaGetSymbolAddress((void**)&c3, g_c3);
    cudaGetSymbolAddress((void**)&c4, g_c4);
    cudaGetSymbolAddress((void**)&c5, g_c5);  cudaGetSymbolAddress((void**)&f0, g_f0);
    cudaGetSymbolAddress((void**)&f1, g_f1);
    cudaGetSymbolAddress((void**)&w0, g_w0);  cudaGetSymbolAddress((void**)&w1, g_w1);
    cudaGetSymbolAddress((void**)&w2, g_w2);  cudaGetSymbolAddress((void**)&w3, g_w3);
    cudaGetSymbolAddress((void**)&w4, g_w4);  cudaGetSymbolAddress((void**)&w5, g_w5);
    cudaGetSymbolAddress((void**)&wf0d, g_wf0); cudaGetSymbolAddress((void**)&wf1d, g_wf1);
    cudaGetSymbolAddress((void**)&wf2d, g_wf2);
    cudaGetSymbolAddress((void**)&bns, g_bns); cudaGetSymbolAddress((void**)&bnm, g_bnm);
    cudaGetSymbolAddress((void**)&bnb, g_bnb);
    cudaGetSymbolAddress((void**)&fns, g_fns); cudaGetSymbolAddress((void**)&fnm, g_fnm);
    cudaGetSymbolAddress((void**)&fnb, g_fnb);

    const int T = 256;
    const int GSM = 64*272 + 128*272;            // 52,224 gemm smem

    // launch 0: all weights + all bn (merged)
    k_prep_all<<<(1545984+T-1)/T, T>>>(wc[0],wc[1],wc[2],wc[3],wc[4],wc[5],
                                       wf[0],wf[1],wf[2],
                                       bnc[0],bnc[1],bnc[2],bnc[3],bnc[4],bnc[5],
                                       bnf[0],bnf[1]);
    // launch 1: conv0 (fused inquant, 4 px/thread)
    k_conv0<<<1024, T>>>(x, w0, bns, bnm, bnb, c0);
    // launch 2: conv1 — OCT=64, AT=2, NIMG=1 (110KB smem, 2 CTA/SM)
    {
        const int SM = 1*900*80 + 64*592;        // 109,888
        cudaFuncSetAttribute(k_cmma<64,64,64,30,30,1,2,false>,
                             cudaFuncAttributeMaxDynamicSharedMemorySize, SM);
        k_cmma<64,64,64,30,30,1,2,false><<<dim3(1024,1), T, SM>>>(c0, w1, bns+256, bnm+256, bnb+256, c1);
    }
    // launch 3: conv2 — OCT=128, NIMG=8, fused pool1, one wave of 128 CTAs
    {
        const int SM = 8*196*80 + 128*592;       // 201,216
        cudaFuncSetAttribute(k_cmma<64,128,128,14,14,8,2,true>,
                             cudaFuncAttributeMaxDynamicSharedMemorySize, SM);
        k_cmma<64,128,128,14,14,8,2,true><<<dim3(128,1), T, SM>>>(c1, w2, bns+512, bnm+512, bnb+512, c2);
    }
    // launch 4: conv3 — NIMG=7, grid (147,2) = 294 CTAs ~ 2 clean waves
    {
        const int SM = 7*144*144 + 64*1168;      // 219,904
        cudaFuncSetAttribute(k_cmma<128,128,64,12,12,7,2,false>,
                             cudaFuncAttributeMaxDynamicSharedMemorySize, SM);
        k_cmma<128,128,64,12,12,7,2,false><<<dim3(147,2), T, SM>>>(c2, w3, bns+768, bnm+768, bnb+768, c3);
    }
    // launch 5: conv4 — NIMG=28, fused pool3 (148 CTAs = 1 wave)
    {
        const int SM = 28*25*144 + 64*1168;      // 175,552
        cudaFuncSetAttribute(k_cmma<128,256,64,5,5,28,2,true>,
                             cudaFuncAttributeMaxDynamicSharedMemorySize, SM);
        k_cmma<128,256,64,5,5,28,2,true><<<dim3(37,4), T, SM>>>(c3, w4, bns+1024, bnm+1024, bnb+1024, c4);
    }
    // launch 6: conv5 as GEMM (M=1024, N=256, K=2304)
    cudaFuncSetAttribute(k_gemm<2304,256>, cudaFuncAttributeMaxDynamicSharedMemorySize, GSM);
    k_gemm<2304,256><<<dim3(16,2), T, GSM>>>(c4, w5, bns+1280, bnm+1280, bnb+1280, c5);
    // launch 7: fc0 (K=256, N=512)
    cudaFuncSetAttribute(k_gemm<256,512>, cudaFuncAttributeMaxDynamicSharedMemorySize, GSM);
    k_gemm<256,512><<<dim3(16,4), T, GSM>>>(c5, wf0d, fns, fnm, fnb, f0);
    // launch 8: fc1 (K=512, N=512)
    cudaFuncSetAttribute(k_gemm<512,512>, cudaFuncAttributeMaxDynamicSharedMemorySize, GSM);
    k_gemm<512,512><<<dim3(16,4), T, GSM>>>(f0, wf1d, fns+512, fnm+512, fnb+512, f1);
    // launch 9: fc2 + TensorNorm
    k_fc_last<<<BSZ, T>>>(f1, wf2d, tn, (float*)d_out);
}